// round 6
// baseline (speedup 1.0000x reference)
#include <cuda_runtime.h>
#include <math.h>

#define Bv   1024
#define DIN  512
#define Hv   1024
#define DOUT 512
#define NBLK 10
#define STEPS 30
#define BH   (Bv*Hv)   // 1<<20

// -------------------- device scratch (no allocations allowed) --------------------
__device__ float g_xemb[BH];          // 4 MB
__device__ float g_h[NBLK*BH];        // 40 MB
__device__ float g_inp[NBLK*BH];      // 40 MB
__device__ float g_hi0[NBLK*BH];      // 40 MB
__device__ float g_hi1[NBLK*BH];      // 40 MB

// -------------------- f32x2 packed-FMA helpers --------------------
__device__ __forceinline__ unsigned long long ffma2(unsigned long long a,
                                                    unsigned long long b,
                                                    unsigned long long c) {
    unsigned long long d;
    asm("fma.rn.f32x2 %0, %1, %2, %3;" : "=l"(d) : "l"(a), "l"(b), "l"(c));
    return d;
}
__device__ __forceinline__ unsigned long long pack2(float x) {
    unsigned long long r;
    unsigned u = __float_as_uint(x);
    asm("mov.b64 %0, {%1, %1};" : "=l"(r) : "r"(u));
    return r;
}

// ============================================================================
// Fused SGEMM:  C[row,col] = sum_k A[row,k] * W[col,k]   (both K-contiguous)
// MODE 0: out = C + bias                                   (embed / head)
// MODE 1: out = 0.5*hi_in + 0.5*tanh(C + bias + inp)       (inner iters 2..4)
// MODE 2: out = 0.5*h     + 0.25*hi_in + 0.25*tanh(C+bias+inp), h==out in place
// ============================================================================
template<int MODE>
__global__ void __launch_bounds__(256)
fgemm(const float* __restrict__ Ag, const float* __restrict__ Wg,
      const float* __restrict__ biasg, const float* __restrict__ inp,
      const float* __restrict__ hi_in, float* __restrict__ outp,
      int M, int N, int K, int first,
      long long zsA, long long zsW, long long zsBias, long long zsC)
{
    const int z = blockIdx.z;
    const float* A    = Ag    + (long long)z * zsA;
    const float* W    = Wg    + (long long)z * zsW;
    const float* bias = biasg + (long long)z * zsBias;
    const long long coff = (long long)z * zsC;

    __shared__ __align__(16) float As[2][16][128];
    __shared__ __align__(16) float Bs[2][16][128];

    const int tid = threadIdx.x;
    const int tx = tid & 15;   // N direction (16)
    const int ty = tid >> 4;   // M direction (16)

    const int lrow = tid >> 2;          // 0..63
    const int lcol = (tid & 3) << 2;    // 0,4,8,12

    const float* aP0 = A + (long long)(blockIdx.y * 128 + lrow) * K + lcol;
    const float* aP1 = aP0 + 64LL * K;
    const float* wP0 = W + (long long)(blockIdx.x * 128 + lrow) * K + lcol;
    const float* wP1 = wP0 + 64LL * K;

    // ---- load K-tile 0 ----
    float4 ra0 = *(const float4*)aP0;
    float4 ra1 = *(const float4*)aP1;
    float4 rb0 = *(const float4*)wP0;
    float4 rb1 = *(const float4*)wP1;

    int buf = 0;
    As[0][lcol+0][lrow]    = ra0.x; As[0][lcol+1][lrow]    = ra0.y;
    As[0][lcol+2][lrow]    = ra0.z; As[0][lcol+3][lrow]    = ra0.w;
    As[0][lcol+0][lrow+64] = ra1.x; As[0][lcol+1][lrow+64] = ra1.y;
    As[0][lcol+2][lrow+64] = ra1.z; As[0][lcol+3][lrow+64] = ra1.w;
    Bs[0][lcol+0][lrow]    = rb0.x; Bs[0][lcol+1][lrow]    = rb0.y;
    Bs[0][lcol+2][lrow]    = rb0.z; Bs[0][lcol+3][lrow]    = rb0.w;
    Bs[0][lcol+0][lrow+64] = rb1.x; Bs[0][lcol+1][lrow+64] = rb1.y;
    Bs[0][lcol+2][lrow+64] = rb1.z; Bs[0][lcol+3][lrow+64] = rb1.w;
    __syncthreads();

    unsigned long long acc[8][4];
#pragma unroll
    for (int i = 0; i < 8; i++)
#pragma unroll
        for (int j = 0; j < 4; j++) acc[i][j] = 0ULL;

    const int ktiles = K >> 4;
    for (int kt = 0; kt < ktiles; ++kt) {
        float4 na0, na1, nb0, nb1;
        const bool more = (kt + 1 < ktiles);
        if (more) {
            const int o = (kt + 1) * 16;
            na0 = *(const float4*)(aP0 + o);
            na1 = *(const float4*)(aP1 + o);
            nb0 = *(const float4*)(wP0 + o);
            nb1 = *(const float4*)(wP1 + o);
        }
#pragma unroll
        for (int k = 0; k < 16; k++) {
            float4 a0 = *(const float4*)&As[buf][k][ty * 4];
            float4 a1 = *(const float4*)&As[buf][k][64 + ty * 4];
            ulonglong2 b0 = *(const ulonglong2*)&Bs[buf][k][tx * 4];
            ulonglong2 b1 = *(const ulonglong2*)&Bs[buf][k][64 + tx * 4];
            unsigned long long bv[4] = {b0.x, b0.y, b1.x, b1.y};
            float av[8] = {a0.x, a0.y, a0.z, a0.w, a1.x, a1.y, a1.z, a1.w};
#pragma unroll
            for (int i = 0; i < 8; i++) {
                unsigned long long a2 = pack2(av[i]);
#pragma unroll
                for (int j = 0; j < 4; j++) acc[i][j] = ffma2(a2, bv[j], acc[i][j]);
            }
        }
        if (more) {
            buf ^= 1;
            As[buf][lcol+0][lrow]    = na0.x; As[buf][lcol+1][lrow]    = na0.y;
            As[buf][lcol+2][lrow]    = na0.z; As[buf][lcol+3][lrow]    = na0.w;
            As[buf][lcol+0][lrow+64] = na1.x; As[buf][lcol+1][lrow+64] = na1.y;
            As[buf][lcol+2][lrow+64] = na1.z; As[buf][lcol+3][lrow+64] = na1.w;
            Bs[buf][lcol+0][lrow]    = nb0.x; Bs[buf][lcol+1][lrow]    = nb0.y;
            Bs[buf][lcol+2][lrow]    = nb0.z; Bs[buf][lcol+3][lrow]    = nb0.w;
            Bs[buf][lcol+0][lrow+64] = nb1.x; Bs[buf][lcol+1][lrow+64] = nb1.y;
            Bs[buf][lcol+2][lrow+64] = nb1.z; Bs[buf][lcol+3][lrow+64] = nb1.w;
            __syncthreads();
        }
    }

    // ---- epilogue ----
#pragma unroll
    for (int i = 0; i < 8; i++) {
        const int row = blockIdx.y * 128 + ((i < 4) ? (ty * 4 + i) : (64 + ty * 4 + i - 4));
        const long long rbase = (long long)row * N;
#pragma unroll
        for (int p = 0; p < 4; p++) {
            const int col = blockIdx.x * 128 +
                            ((p < 2) ? (tx * 4 + p * 2) : (64 + tx * 4 + (p - 2) * 2));
            const float vlo = __uint_as_float((unsigned)acc[i][p]);
            const float vhi = __uint_as_float((unsigned)(acc[i][p] >> 32));
            if (MODE == 0) {
                outp[rbase + col]     = vlo + bias[col];
                outp[rbase + col + 1] = vhi + bias[col + 1];
            } else {
                const long long idx = coff + rbase + col;
                const float2 ip = *(const float2*)&inp[idx];
                const float2 hv = *(const float2*)&hi_in[idx];
                const float plo = vlo + bias[col]     + ip.x;
                const float phi = vhi + bias[col + 1] + ip.y;
                if (MODE == 1) {
                    float2 o;
                    o.x = 0.5f * hv.x + 0.5f * tanhf(plo);
                    o.y = 0.5f * hv.y + 0.5f * tanhf(phi);
                    *(float2*)&outp[idx] = o;
                } else {
                    float2 hc;
                    if (first) { hc.x = 0.f; hc.y = 0.f; }
                    else       { hc = *(const float2*)&outp[idx]; }
                    float2 o;
                    o.x = 0.5f * hc.x + 0.25f * hv.x + 0.25f * tanhf(plo);
                    o.y = 0.5f * hc.y + 0.25f * hv.y + 0.25f * tanhf(phi);
                    *(float2*)&outp[idx] = o;
                }
            }
        }
    }
}

// ============================================================================
// Per-outer-step prep:
//   inp[n] = h[n] + (n==0 ? x_emb : h[n-1])       (h treated as 0 when first)
//   hi0[n] = 0.5 * tanh(block_b[n] + inp[n])      (inner iteration 1, GEMM-free)
// ============================================================================
__global__ void __launch_bounds__(256)
prep_kernel(const float* __restrict__ blockb, int first)
{
    const long long t = (long long)blockIdx.x * blockDim.x + threadIdx.x;
    const long long total = (long long)NBLK * BH / 4;
    if (t >= total) return;
    const long long e = t << 2;
    const int n = (int)(e >> 20);          // BH == 1<<20
    const long long r = e & (BH - 1);
    const int d = (int)(e & (Hv - 1));

    float4 hv, bi;
    if (first) hv = make_float4(0.f, 0.f, 0.f, 0.f);
    else       hv = *(const float4*)&g_h[e];
    if (n == 0)      bi = *(const float4*)&g_xemb[r];
    else if (first)  bi = make_float4(0.f, 0.f, 0.f, 0.f);
    else             bi = *(const float4*)&g_h[e - BH];

    float4 v;
    v.x = hv.x + bi.x; v.y = hv.y + bi.y; v.z = hv.z + bi.z; v.w = hv.w + bi.w;
    *(float4*)&g_inp[e] = v;

    const float4 bb = *(const float4*)&blockb[n * Hv + d];
    float4 o;
    o.x = 0.5f * tanhf(bb.x + v.x);
    o.y = 0.5f * tanhf(bb.y + v.y);
    o.z = 0.5f * tanhf(bb.z + v.z);
    o.w = 0.5f * tanhf(bb.w + v.w);
    *(float4*)&g_hi0[e] = o;
}

// ============================================================================
extern "C" void kernel_launch(void* const* d_in, const int* in_sizes, int n_in,
                              void* d_out, int out_size)
{
    const float* x     = (const float*)d_in[0];  // (B, DIN)
    const float* embW  = (const float*)d_in[1];  // (H, DIN)
    const float* embB  = (const float*)d_in[2];  // (H)
    const float* blkW  = (const float*)d_in[3];  // (NB, H, H)
    const float* blkB  = (const float*)d_in[4];  // (NB, H)
    const float* headW = (const float*)d_in[5];  // (DOUT, H)
    const float* headB = (const float*)d_in[6];  // (DOUT)
    float* out = (float*)d_out;                  // (B, DOUT)

    float *xemb, *h, *inp, *hi0, *hi1;
    cudaGetSymbolAddress((void**)&xemb, g_xemb);
    cudaGetSymbolAddress((void**)&h,    g_h);
    cudaGetSymbolAddress((void**)&inp,  g_inp);
    cudaGetSymbolAddress((void**)&hi0,  g_hi0);
    cudaGetSymbolAddress((void**)&hi1,  g_hi1);

    const dim3 blk(256);

    // embed: x_emb = x @ embW^T + embB    (M=B, N=H, K=DIN)
    fgemm<0><<<dim3(Hv / 128, Bv / 128, 1), blk>>>(
        x, embW, embB, nullptr, nullptr, xemb,
        Bv, Hv, DIN, 0, 0LL, 0LL, 0LL, 0LL);

    const long long zsA = BH, zsW = (long long)Hv * Hv, zsB2 = Hv, zsC = BH;
    const dim3 g(Hv / 128, Bv / 128, NBLK);
    const int prep_blocks = (NBLK * BH / 4) / 256;

    for (int s = 0; s < STEPS; ++s) {
        const int first = (s == 0) ? 1 : 0;
        prep_kernel<<<prep_blocks, blk>>>(blkB, first);
        // inner iterations 2..4 (ping-pong hi buffers)
        fgemm<1><<<g, blk>>>(hi0, blkW, blkB, inp, hi0, hi1, Bv, Hv, Hv, 0, zsA, zsW, zsB2, zsC);
        fgemm<1><<<g, blk>>>(hi1, blkW, blkB, inp, hi1, hi0, Bv, Hv, Hv, 0, zsA, zsW, zsB2, zsC);
        fgemm<1><<<g, blk>>>(hi0, blkW, blkB, inp, hi0, hi1, Bv, Hv, Hv, 0, zsA, zsW, zsB2, zsC);
        // inner iteration 5 fused with outer update: h = 0.5h + 0.25 hi + 0.25 tanh(pre)
        fgemm<2><<<g, blk>>>(hi1, blkW, blkB, inp, hi1, h,   Bv, Hv, Hv, first, zsA, zsW, zsB2, zsC);
    }

    // head: out = h[NB-1] @ headW^T + headB   (M=B, N=DOUT, K=H)
    fgemm<0><<<dim3(DOUT / 128, Bv / 128, 1), blk>>>(
        h + (long long)(NBLK - 1) * BH, headW, headB, nullptr, nullptr, out,
        Bv, DOUT, Hv, 0, 0LL, 0LL, 0LL, 0LL);
}

// round 9
// speedup vs baseline: 1.8576x; 1.8576x over previous
#include <cuda_runtime.h>
#include <cuda_bf16.h>
#include <cstdint>
#include <math.h>

#define Bv   1024
#define DIN  512
#define Hv   1024
#define DOUT 512
#define NBLK 10
#define STEPS 30
#define BH   (Bv*Hv)   // 1<<20

// -------------------- device scratch (no allocations allowed) --------------------
__device__ float g_xemb[BH];                     // 4 MB
__device__ float g_h[NBLK*BH];                   // 40 MB fp32 outer state
__device__ float g_inp[NBLK*BH];                 // 40 MB fp32 inner additive input
__device__ __nv_bfloat16 g_hiA[NBLK*BH];         // activation hi, ping
__device__ __nv_bfloat16 g_loA[NBLK*BH];         // activation lo, ping
__device__ __nv_bfloat16 g_hiB[NBLK*BH];         // pong
__device__ __nv_bfloat16 g_loB[NBLK*BH];
__device__ __nv_bfloat16 g_Whi[NBLK*Hv*Hv];      // weight hi
__device__ __nv_bfloat16 g_Wlo[NBLK*Hv*Hv];      // weight lo

// ============================================================================
// baseline-PTX helpers (no sm_103a-only features!)
// ============================================================================
__device__ __forceinline__ uint32_t smem_u32(const void* p) {
    uint32_t a;
    asm("{ .reg .u64 t; cvta.to.shared.u64 t, %1; cvt.u32.u64 %0, t; }"
        : "=r"(a) : "l"(p));
    return a;
}
#define CP_ASYNC16(saddr, gptr) \
    asm volatile("cp.async.cg.shared.global [%0], [%1], 16;" \
                 :: "r"(saddr), "l"(gptr) : "memory")
#define CP_COMMIT() asm volatile("cp.async.commit_group;" ::: "memory")
#define CP_WAIT(N)  asm volatile("cp.async.wait_group %0;" :: "n"(N) : "memory")

#define LDSM4(r, addr) \
    asm volatile("ldmatrix.sync.aligned.m8n8.x4.shared.b16 {%0,%1,%2,%3}, [%4];" \
                 : "=r"((r)[0]), "=r"((r)[1]), "=r"((r)[2]), "=r"((r)[3]) \
                 : "r"(addr))

__device__ __forceinline__ void mma_bf16(float* c, const uint32_t* a,
                                         uint32_t b0, uint32_t b1) {
    asm volatile("mma.sync.aligned.m16n8k16.row.col.f32.bf16.bf16.f32 "
                 "{%0,%1,%2,%3}, {%4,%5,%6,%7}, {%8,%9}, {%0,%1,%2,%3};"
                 : "+f"(c[0]), "+f"(c[1]), "+f"(c[2]), "+f"(c[3])
                 : "r"(a[0]), "r"(a[1]), "r"(a[2]), "r"(a[3]), "r"(b0), "r"(b1));
}

// SMEM tile layout: 4 sub-tiles (Ahi, Alo, Bhi, Blo), each 128 rows x 32 bf16,
// padded to 40 bf16 (80 B) per row => conflict-free ldmatrix, 16B-aligned rows.
#define SUB_BYTES 10240              // 128 * 80
#define BUF_BYTES (4 * SUB_BYTES)    // 40960
#define SMEM_DYN  (2 * BUF_BYTES)    // 81920

// ============================================================================
// bf16x3 split GEMM. CTA tile 128(M) x 128(N), K=1024, BK=32, 8 warps (2x4).
// D = Ahi*Whi + Alo*Whi + Ahi*Wlo  (fp32 accum)
// MODE 1: o = 0.5*(hi+lo)[in] + 0.5*tanh(D + bias + inp)  -> split -> Ohi/Olo
// MODE 2: o = 0.5*H + 0.25*(hi+lo)[in] + 0.25*tanh(D+bias+inp) -> H (fp32)
// ============================================================================
template<int MODE>
__global__ void __launch_bounds__(256, 1)
tgemm(const __nv_bfloat16* __restrict__ Ahi, const __nv_bfloat16* __restrict__ Alo,
      const __nv_bfloat16* __restrict__ Whi, const __nv_bfloat16* __restrict__ Wlo,
      const float* __restrict__ bias, const float* __restrict__ inp,
      __nv_bfloat16* __restrict__ Ohi, __nv_bfloat16* __restrict__ Olo,
      float* __restrict__ Hbuf, int first)
{
    extern __shared__ __align__(1024) char sm[];
    const uint32_t smBase = smem_u32(sm);

    const int tid = threadIdx.x;
    const int wid = tid >> 5, lid = tid & 31;
    const int wm = wid >> 2, wn = wid & 3;       // warp grid 2(M) x 4(N)
    const int bX = blockIdx.x;                   // N tile
    const int bY = blockIdx.y;                   // M tile
    const int z  = blockIdx.z;

    const long long aBase = (long long)z * BH + (long long)bY * 128 * 1024;
    const long long wBase = (long long)z * (Hv * Hv) + (long long)bX * 128 * 1024;

    // ---- cp.async tile loader lane mapping (fully static) ----
    const int chk = tid & 3;          // 16B chunk within 64B of K
    const int r0  = tid >> 2;         // 0..63

    // ---- ldmatrix lane base offsets (within a buffer) ----
    const uint32_t aLane = (uint32_t)((wm * 64 + (lid & 15)) * 80 + (lid >> 4) * 16);
    const int bq = lid >> 3;
    const uint32_t bLane = (uint32_t)(2 * SUB_BYTES +
                          (wn * 32 + ((bq >> 1) * 8) + (lid & 7)) * 80 + (bq & 1) * 16);

    float acc[4][4][4];
#pragma unroll
    for (int i = 0; i < 4; i++)
#pragma unroll
        for (int j = 0; j < 4; j++)
#pragma unroll
            for (int q = 0; q < 4; q++) acc[i][j][q] = 0.f;

    auto issue_loads = [&](int kt, int buf) {
        const uint32_t sBuf = smBase + buf * BUF_BYTES;
#pragma unroll
        for (int i = 0; i < 8; i++) {
            const int sub = i >> 1;                 // 0:Ahi 1:Alo 2:Bhi 3:Blo
            const int row = (i & 1) * 64 + r0;
            const __nv_bfloat16* g;
            if (sub == 0)      g = Ahi + aBase;
            else if (sub == 1) g = Alo + aBase;
            else if (sub == 2) g = Whi + wBase;
            else               g = Wlo + wBase;
            g += (long long)row * 1024 + kt * 32 + chk * 8;
            const uint32_t s = sBuf + sub * SUB_BYTES + row * 80 + chk * 16;
            CP_ASYNC16(s, g);
        }
        CP_COMMIT();
    };

    issue_loads(0, 0);

    for (int kt = 0; kt < 32; kt++) {
        const int buf = kt & 1;
        if (kt + 1 < 32) {
            issue_loads(kt + 1, buf ^ 1);
            CP_WAIT(1);
        } else {
            CP_WAIT(0);
        }
        __syncthreads();

        const uint32_t sBuf = smBase + buf * BUF_BYTES;
        const uint32_t aA = sBuf + aLane;
        const uint32_t aB = sBuf + bLane;
#pragma unroll
        for (int ks = 0; ks < 2; ks++) {
            uint32_t ah[4][4], al[4][4], bh[2][4], bl[2][4];
#pragma unroll
            for (int i = 0; i < 4; i++) {
                LDSM4(ah[i], aA + i * (16 * 80) + ks * 32);
                LDSM4(al[i], aA + SUB_BYTES + i * (16 * 80) + ks * 32);
            }
#pragma unroll
            for (int p = 0; p < 2; p++) {
                LDSM4(bh[p], aB + p * (16 * 80) + ks * 32);
                LDSM4(bl[p], aB + SUB_BYTES + p * (16 * 80) + ks * 32);
            }
#pragma unroll
            for (int i = 0; i < 4; i++)
#pragma unroll
                for (int j = 0; j < 4; j++) {
                    const int p = j >> 1, hh = (j & 1) * 2;
                    mma_bf16(acc[i][j], ah[i], bh[p][hh], bh[p][hh + 1]);
                    mma_bf16(acc[i][j], al[i], bh[p][hh], bh[p][hh + 1]);
                    mma_bf16(acc[i][j], ah[i], bl[p][hh], bl[p][hh + 1]);
                }
        }
        __syncthreads();
    }

    // ---- fused epilogue ----
    const long long zb = (long long)z * BH;
    const int er = lid >> 2, ec = (lid & 3) * 2;
#pragma unroll
    for (int i = 0; i < 4; i++) {
#pragma unroll
        for (int j = 0; j < 4; j++) {
            const int col = bX * 128 + wn * 32 + j * 8 + ec;
            const float2 bv = *(const float2*)(bias + z * Hv + col);
#pragma unroll
            for (int half = 0; half < 2; half++) {
                const int row = bY * 128 + wm * 64 + i * 16 + er + half * 8;
                const long long idx = zb + (long long)row * 1024 + col;
                const float c0 = acc[i][j][half * 2 + 0];
                const float c1 = acc[i][j][half * 2 + 1];
                const float2 iv = *(const float2*)(inp + idx);
                const __nv_bfloat162 hv2 = *(const __nv_bfloat162*)(Ahi + idx);
                const __nv_bfloat162 lv2 = *(const __nv_bfloat162*)(Alo + idx);
                const float hin0 = __bfloat162float(hv2.x) + __bfloat162float(lv2.x);
                const float hin1 = __bfloat162float(hv2.y) + __bfloat162float(lv2.y);
                const float pre0 = c0 + bv.x + iv.x;
                const float pre1 = c1 + bv.y + iv.y;
                if (MODE == 1) {
                    const float o0 = 0.5f * hin0 + 0.5f * tanhf(pre0);
                    const float o1 = 0.5f * hin1 + 0.5f * tanhf(pre1);
                    const __nv_bfloat16 h0 = __float2bfloat16(o0);
                    const __nv_bfloat16 h1 = __float2bfloat16(o1);
                    const __nv_bfloat16 l0 = __float2bfloat16(o0 - __bfloat162float(h0));
                    const __nv_bfloat16 l1 = __float2bfloat16(o1 - __bfloat162float(h1));
                    *(__nv_bfloat162*)(Ohi + idx) = __halves2bfloat162(h0, h1);
                    *(__nv_bfloat162*)(Olo + idx) = __halves2bfloat162(l0, l1);
                } else {
                    float2 hc = first ? make_float2(0.f, 0.f)
                                      : *(const float2*)(Hbuf + idx);
                    float2 o;
                    o.x = 0.5f * hc.x + 0.25f * hin0 + 0.25f * tanhf(pre0);
                    o.y = 0.5f * hc.y + 0.25f * hin1 + 0.25f * tanhf(pre1);
                    *(float2*)(Hbuf + idx) = o;
                }
            }
        }
    }
}

// ============================================================================
// FFMA2 SGEMM: out = A @ W^T + bias  (fp32, embed / head)
// ============================================================================
__device__ __forceinline__ unsigned long long ffma2(unsigned long long a,
                                                    unsigned long long b,
                                                    unsigned long long c) {
    unsigned long long d;
    asm("fma.rn.f32x2 %0, %1, %2, %3;" : "=l"(d) : "l"(a), "l"(b), "l"(c));
    return d;
}
__device__ __forceinline__ unsigned long long pack2(float x) {
    unsigned long long r;
    unsigned u = __float_as_uint(x);
    asm("mov.b64 %0, {%1, %1};" : "=l"(r) : "r"(u));
    return r;
}

__global__ void __launch_bounds__(256)
fgemm0(const float* __restrict__ A, const float* __restrict__ W,
       const float* __restrict__ bias, float* __restrict__ outp, int N, int K)
{
    __shared__ __align__(16) float As[2][16][128];
    __shared__ __align__(16) float Bs[2][16][128];
    const int tid = threadIdx.x;
    const int tx = tid & 15, ty = tid >> 4;
    const int lrow = tid >> 2, lcol = (tid & 3) << 2;

    const float* aP0 = A + (long long)(blockIdx.y * 128 + lrow) * K + lcol;
    const float* aP1 = aP0 + 64LL * K;
    const float* wP0 = W + (long long)(blockIdx.x * 128 + lrow) * K + lcol;
    const float* wP1 = wP0 + 64LL * K;

    float4 ra0 = *(const float4*)aP0, ra1 = *(const float4*)aP1;
    float4 rb0 = *(const float4*)wP0, rb1 = *(const float4*)wP1;
    int buf = 0;
    As[0][lcol+0][lrow]=ra0.x; As[0][lcol+1][lrow]=ra0.y; As[0][lcol+2][lrow]=ra0.z; As[0][lcol+3][lrow]=ra0.w;
    As[0][lcol+0][lrow+64]=ra1.x; As[0][lcol+1][lrow+64]=ra1.y; As[0][lcol+2][lrow+64]=ra1.z; As[0][lcol+3][lrow+64]=ra1.w;
    Bs[0][lcol+0][lrow]=rb0.x; Bs[0][lcol+1][lrow]=rb0.y; Bs[0][lcol+2][lrow]=rb0.z; Bs[0][lcol+3][lrow]=rb0.w;
    Bs[0][lcol+0][lrow+64]=rb1.x; Bs[0][lcol+1][lrow+64]=rb1.y; Bs[0][lcol+2][lrow+64]=rb1.z; Bs[0][lcol+3][lrow+64]=rb1.w;
    __syncthreads();

    unsigned long long acc[8][4];
#pragma unroll
    for (int i = 0; i < 8; i++)
#pragma unroll
        for (int j = 0; j < 4; j++) acc[i][j] = 0ULL;

    const int ktiles = K >> 4;
    for (int kt = 0; kt < ktiles; ++kt) {
        float4 na0, na1, nb0, nb1;
        const bool more = (kt + 1 < ktiles);
        if (more) {
            const int o = (kt + 1) * 16;
            na0 = *(const float4*)(aP0 + o); na1 = *(const float4*)(aP1 + o);
            nb0 = *(const float4*)(wP0 + o); nb1 = *(const float4*)(wP1 + o);
        }
#pragma unroll
        for (int k = 0; k < 16; k++) {
            float4 a0 = *(const float4*)&As[buf][k][ty * 4];
            float4 a1 = *(const float4*)&As[buf][k][64 + ty * 4];
            ulonglong2 b0 = *(const ulonglong2*)&Bs[buf][k][tx * 4];
            ulonglong2 b1 = *(const ulonglong2*)&Bs[buf][k][64 + tx * 4];
            unsigned long long bv[4] = {b0.x, b0.y, b1.x, b1.y};
            float av[8] = {a0.x, a0.y, a0.z, a0.w, a1.x, a1.y, a1.z, a1.w};
#pragma unroll
            for (int i = 0; i < 8; i++) {
                unsigned long long a2 = pack2(av[i]);
#pragma unroll
                for (int j = 0; j < 4; j++) acc[i][j] = ffma2(a2, bv[j], acc[i][j]);
            }
        }
        if (more) {
            buf ^= 1;
            As[buf][lcol+0][lrow]=na0.x; As[buf][lcol+1][lrow]=na0.y; As[buf][lcol+2][lrow]=na0.z; As[buf][lcol+3][lrow]=na0.w;
            As[buf][lcol+0][lrow+64]=na1.x; As[buf][lcol+1][lrow+64]=na1.y; As[buf][lcol+2][lrow+64]=na1.z; As[buf][lcol+3][lrow+64]=na1.w;
            Bs[buf][lcol+0][lrow]=nb0.x; Bs[buf][lcol+1][lrow]=nb0.y; Bs[buf][lcol+2][lrow]=nb0.z; Bs[buf][lcol+3][lrow]=nb0.w;
            Bs[buf][lcol+0][lrow+64]=nb1.x; Bs[buf][lcol+1][lrow+64]=nb1.y; Bs[buf][lcol+2][lrow+64]=nb1.z; Bs[buf][lcol+3][lrow+64]=nb1.w;
            __syncthreads();
        }
    }
#pragma unroll
    for (int i = 0; i < 8; i++) {
        const int row = blockIdx.y * 128 + ((i < 4) ? (ty * 4 + i) : (64 + ty * 4 + i - 4));
        const long long rbase = (long long)row * N;
#pragma unroll
        for (int p = 0; p < 4; p++) {
            const int col = blockIdx.x * 128 +
                            ((p < 2) ? (tx * 4 + p * 2) : (64 + tx * 4 + (p - 2) * 2));
            outp[rbase + col]     = __uint_as_float((unsigned)acc[i][p])         + bias[col];
            outp[rbase + col + 1] = __uint_as_float((unsigned)(acc[i][p] >> 32)) + bias[col + 1];
        }
    }
}

// ============================================================================
// Weight split: Whi/Wlo = bf16 hi/lo of block_W
// ============================================================================
__global__ void __launch_bounds__(256)
wsplit_kernel(const float* __restrict__ w)
{
    const long long e = ((long long)blockIdx.x * blockDim.x + threadIdx.x) << 2;
    const float4 v = *(const float4*)(w + e);
    __nv_bfloat16 h0 = __float2bfloat16(v.x), h1 = __float2bfloat16(v.y);
    __nv_bfloat16 h2 = __float2bfloat16(v.z), h3 = __float2bfloat16(v.w);
    __nv_bfloat16 l0 = __float2bfloat16(v.x - __bfloat162float(h0));
    __nv_bfloat16 l1 = __float2bfloat16(v.y - __bfloat162float(h1));
    __nv_bfloat16 l2 = __float2bfloat16(v.z - __bfloat162float(h2));
    __nv_bfloat16 l3 = __float2bfloat16(v.w - __bfloat162float(h3));
    ((__nv_bfloat162*)(g_Whi + e))[0] = __halves2bfloat162(h0, h1);
    ((__nv_bfloat162*)(g_Whi + e))[1] = __halves2bfloat162(h2, h3);
    ((__nv_bfloat162*)(g_Wlo + e))[0] = __halves2bfloat162(l0, l1);
    ((__nv_bfloat162*)(g_Wlo + e))[1] = __halves2bfloat162(l2, l3);
}

// ============================================================================
// Per-outer-step prep:
//   inp[n] = h[n] + (n==0 ? x_emb : h[n-1])   (h==0 on first step)
//   hi/loA = split( 0.5 * tanh(block_b[n] + inp[n]) )   (inner iter 1)
// ============================================================================
__global__ void __launch_bounds__(256)
prep_kernel(const float* __restrict__ blockb, int first)
{
    const long long e = ((long long)blockIdx.x * blockDim.x + threadIdx.x) << 2;
    const int n = (int)(e >> 20);
    const long long r = e & (BH - 1);
    const int d = (int)(e & (Hv - 1));

    float4 hv, bi;
    if (first) hv = make_float4(0.f, 0.f, 0.f, 0.f);
    else       hv = *(const float4*)&g_h[e];
    if (n == 0)      bi = *(const float4*)&g_xemb[r];
    else if (first)  bi = make_float4(0.f, 0.f, 0.f, 0.f);
    else             bi = *(const float4*)&g_h[e - BH];

    float4 v;
    v.x = hv.x + bi.x; v.y = hv.y + bi.y; v.z = hv.z + bi.z; v.w = hv.w + bi.w;
    *(float4*)&g_inp[e] = v;

    const float4 bb = *(const float4*)&blockb[n * Hv + d];
    const float t0 = 0.5f * tanhf(bb.x + v.x);
    const float t1 = 0.5f * tanhf(bb.y + v.y);
    const float t2 = 0.5f * tanhf(bb.z + v.z);
    const float t3 = 0.5f * tanhf(bb.w + v.w);
    __nv_bfloat16 h0 = __float2bfloat16(t0), h1 = __float2bfloat16(t1);
    __nv_bfloat16 h2 = __float2bfloat16(t2), h3 = __float2bfloat16(t3);
    __nv_bfloat16 l0 = __float2bfloat16(t0 - __bfloat162float(h0));
    __nv_bfloat16 l1 = __float2bfloat16(t1 - __bfloat162float(h1));
    __nv_bfloat16 l2 = __float2bfloat16(t2 - __bfloat162float(h2));
    __nv_bfloat16 l3 = __float2bfloat16(t3 - __bfloat162float(h3));
    ((__nv_bfloat162*)(g_hiA + e))[0] = __halves2bfloat162(h0, h1);
    ((__nv_bfloat162*)(g_hiA + e))[1] = __halves2bfloat162(h2, h3);
    ((__nv_bfloat162*)(g_loA + e))[0] = __halves2bfloat162(l0, l1);
    ((__nv_bfloat162*)(g_loA + e))[1] = __halves2bfloat162(l2, l3);
}

// ============================================================================
extern "C" void kernel_launch(void* const* d_in, const int* in_sizes, int n_in,
                              void* d_out, int out_size)
{
    const float* x     = (const float*)d_in[0];  // (B, DIN)
    const float* embW  = (const float*)d_in[1];  // (H, DIN)
    const float* embB  = (const float*)d_in[2];  // (H)
    const float* blkW  = (const float*)d_in[3];  // (NB, H, H)
    const float* blkB  = (const float*)d_in[4];  // (NB, H)
    const float* headW = (const float*)d_in[5];  // (DOUT, H)
    const float* headB = (const float*)d_in[6];  // (DOUT)
    float* out = (float*)d_out;                  // (B, DOUT)

    float *xemb, *h, *inp;
    __nv_bfloat16 *hiA, *loA, *hiB, *loB, *Whi, *Wlo;
    cudaGetSymbolAddress((void**)&xemb, g_xemb);
    cudaGetSymbolAddress((void**)&h,    g_h);
    cudaGetSymbolAddress((void**)&inp,  g_inp);
    cudaGetSymbolAddress((void**)&hiA,  g_hiA);
    cudaGetSymbolAddress((void**)&loA,  g_loA);
    cudaGetSymbolAddress((void**)&hiB,  g_hiB);
    cudaGetSymbolAddress((void**)&loB,  g_loB);
    cudaGetSymbolAddress((void**)&Whi,  g_Whi);
    cudaGetSymbolAddress((void**)&Wlo,  g_Wlo);

    cudaFuncSetAttribute(tgemm<1>, cudaFuncAttributeMaxDynamicSharedMemorySize, SMEM_DYN);
    cudaFuncSetAttribute(tgemm<2>, cudaFuncAttributeMaxDynamicSharedMemorySize, SMEM_DYN);

    const dim3 blk(256);

    // split weights into bf16 hi/lo (once per call)
    wsplit_kernel<<<(NBLK * Hv * Hv / 4) / 256, blk>>>(blkW);

    // embed: x_emb = x @ embW^T + embB   (M=B, N=H, K=DIN)
    fgemm0<<<dim3(Hv / 128, Bv / 128, 1), blk>>>(x, embW, embB, xemb, Hv, DIN);

    const dim3 g(Hv / 128, Bv / 128, NBLK);   // (8, 8, 10)
    const int prep_blocks = (NBLK * BH / 4) / 256;

    for (int s = 0; s < STEPS; ++s) {
        const int first = (s == 0) ? 1 : 0;
        prep_kernel<<<prep_blocks, blk>>>(blkB, first);
        // inner iterations 2..4 (ping-pong hi/lo buffers)
        tgemm<1><<<g, blk, SMEM_DYN>>>(hiA, loA, Whi, Wlo, blkB, inp, hiB, loB, nullptr, 0);
        tgemm<1><<<g, blk, SMEM_DYN>>>(hiB, loB, Whi, Wlo, blkB, inp, hiA, loA, nullptr, 0);
        tgemm<1><<<g, blk, SMEM_DYN>>>(hiA, loA, Whi, Wlo, blkB, inp, hiB, loB, nullptr, 0);
        // inner iteration 5 fused with outer update
        tgemm<2><<<g, blk, SMEM_DYN>>>(hiB, loB, Whi, Wlo, blkB, inp, nullptr, nullptr, h, first);
    }

    // head: out = h[NB-1] @ headW^T + headB   (M=B, N=DOUT, K=H)
    fgemm0<<<dim3(DOUT / 128, Bv / 128, 1), blk>>>(
        h + (long long)(NBLK - 1) * BH, headW, headB, out, DOUT, Hv);
}

// round 11
// speedup vs baseline: 2.3802x; 1.2813x over previous
#include <cuda_runtime.h>
#include <cuda_bf16.h>
#include <cstdint>
#include <math.h>

#define Bv   1024
#define DIN  512
#define Hv   1024
#define DOUT 512
#define NBLK 10
#define STEPS 30
#define BH   (Bv*Hv)   // 1<<20

// -------------------- device scratch (no allocations allowed) --------------------
__device__ float g_xemb[BH];                     // 4 MB
__device__ float g_h[NBLK*BH];                   // 40 MB fp32 outer state
__device__ float g_inp[NBLK*BH];                 // 40 MB fp32 inner additive input
__device__ __nv_bfloat16 g_hiA[NBLK*BH];         // activation hi, ping
__device__ __nv_bfloat16 g_loA[NBLK*BH];         // activation lo, ping
__device__ __nv_bfloat16 g_hiB[NBLK*BH];         // pong
__device__ __nv_bfloat16 g_loB[NBLK*BH];
__device__ __nv_bfloat16 g_Whi[NBLK*Hv*Hv];      // weight hi
__device__ __nv_bfloat16 g_Wlo[NBLK*Hv*Hv];      // weight lo

// ============================================================================
// baseline-PTX helpers (no sm_103a-only features!)
// ============================================================================
__device__ __forceinline__ uint32_t smem_u32(const void* p) {
    uint32_t a;
    asm("{ .reg .u64 t; cvta.to.shared.u64 t, %1; cvt.u32.u64 %0, t; }"
        : "=r"(a) : "l"(p));
    return a;
}
#define CP_ASYNC16(saddr, gptr) \
    asm volatile("cp.async.cg.shared.global [%0], [%1], 16;" \
                 :: "r"(saddr), "l"(gptr) : "memory")
#define CP_COMMIT() asm volatile("cp.async.commit_group;" ::: "memory")
#define CP_WAIT(N)  asm volatile("cp.async.wait_group %0;" :: "n"(N) : "memory")

#define LDSM4(r, addr) \
    asm volatile("ldmatrix.sync.aligned.m8n8.x4.shared.b16 {%0,%1,%2,%3}, [%4];" \
                 : "=r"((r)[0]), "=r"((r)[1]), "=r"((r)[2]), "=r"((r)[3]) \
                 : "r"(addr))

__device__ __forceinline__ void mma_bf16(float* c, const uint32_t* a,
                                         uint32_t b0, uint32_t b1) {
    asm volatile("mma.sync.aligned.m16n8k16.row.col.f32.bf16.bf16.f32 "
                 "{%0,%1,%2,%3}, {%4,%5,%6,%7}, {%8,%9}, {%0,%1,%2,%3};"
                 : "+f"(c[0]), "+f"(c[1]), "+f"(c[2]), "+f"(c[3])
                 : "r"(a[0]), "r"(a[1]), "r"(a[2]), "r"(a[3]), "r"(b0), "r"(b1));
}

// SMEM tile layout: 4 sub-tiles (Ahi, Alo, Bhi, Blo), each 128 rows x 32 bf16,
// padded to 40 bf16 (80 B) per row => conflict-free ldmatrix, 16B-aligned rows.
#define SUB_BYTES 10240              // 128 * 80
#define BUF_BYTES (4 * SUB_BYTES)    // 40960
#define SMEM_DYN  (2 * BUF_BYTES)    // 81920

// ============================================================================
// bf16x3 split GEMM. CTA tile 128(M) x 128(N), K=1024, BK=32, 8 warps (2x4).
// 2 CTAs/SM co-resident (regs capped at 128 via launch bounds; fragment
// pressure lowered by serializing the three MMA groups).
// D = Ahi*Whi + Alo*Whi + Ahi*Wlo  (fp32 accum)
// MODE 1: o = 0.5*(hi+lo)[in] + 0.5*tanh(D + bias + inp)  -> split -> Ohi/Olo
// MODE 2: o = 0.5*H + 0.25*(hi+lo)[in] + 0.25*tanh(D+bias+inp) -> H (fp32)
// ============================================================================
template<int MODE>
__global__ void __launch_bounds__(256, 2)
tgemm(const __nv_bfloat16* __restrict__ Ahi, const __nv_bfloat16* __restrict__ Alo,
      const __nv_bfloat16* __restrict__ Whi, const __nv_bfloat16* __restrict__ Wlo,
      const float* __restrict__ bias, const float* __restrict__ inp,
      __nv_bfloat16* __restrict__ Ohi, __nv_bfloat16* __restrict__ Olo,
      float* __restrict__ Hbuf, int first)
{
    extern __shared__ __align__(1024) char sm[];
    const uint32_t smBase = smem_u32(sm);

    const int tid = threadIdx.x;
    const int wid = tid >> 5, lid = tid & 31;
    const int wm = wid >> 2, wn = wid & 3;       // warp grid 2(M) x 4(N)
    const int bX = blockIdx.x;                   // N tile
    const int bY = blockIdx.y;                   // M tile
    const int z  = blockIdx.z;

    const long long aBase = (long long)z * BH + (long long)bY * 128 * 1024;
    const long long wBase = (long long)z * (Hv * Hv) + (long long)bX * 128 * 1024;

    // ---- cp.async tile loader lane mapping (fully static) ----
    const int chk = tid & 3;          // 16B chunk within 64B of K
    const int r0  = tid >> 2;         // 0..63

    // ---- ldmatrix lane base offsets (within a buffer) ----
    const uint32_t aLane = (uint32_t)((wm * 64 + (lid & 15)) * 80 + (lid >> 4) * 16);
    const int bq = lid >> 3;
    const uint32_t bLane = (uint32_t)(2 * SUB_BYTES +
                          (wn * 32 + ((bq >> 1) * 8) + (lid & 7)) * 80 + (bq & 1) * 16);

    float acc[4][4][4];
#pragma unroll
    for (int i = 0; i < 4; i++)
#pragma unroll
        for (int j = 0; j < 4; j++)
#pragma unroll
            for (int q = 0; q < 4; q++) acc[i][j][q] = 0.f;

    auto issue_loads = [&](int kt, int buf) {
        const uint32_t sBuf = smBase + buf * BUF_BYTES;
#pragma unroll
        for (int i = 0; i < 8; i++) {
            const int sub = i >> 1;                 // 0:Ahi 1:Alo 2:Bhi 3:Blo
            const int row = (i & 1) * 64 + r0;
            const __nv_bfloat16* g;
            if (sub == 0)      g = Ahi + aBase;
            else if (sub == 1) g = Alo + aBase;
            else if (sub == 2) g = Whi + wBase;
            else               g = Wlo + wBase;
            g += (long long)row * 1024 + kt * 32 + chk * 8;
            const uint32_t s = sBuf + sub * SUB_BYTES + row * 80 + chk * 16;
            CP_ASYNC16(s, g);
        }
        CP_COMMIT();
    };

    issue_loads(0, 0);

    for (int kt = 0; kt < 32; kt++) {
        const int buf = kt & 1;
        if (kt + 1 < 32) {
            issue_loads(kt + 1, buf ^ 1);
            CP_WAIT(1);
        } else {
            CP_WAIT(0);
        }
        __syncthreads();

        const uint32_t sBuf = smBase + buf * BUF_BYTES;
        const uint32_t aA = sBuf + aLane;
        const uint32_t aB = sBuf + bLane;
#pragma unroll
        for (int ks = 0; ks < 2; ks++) {
            // group 1: Ahi x Bhi   (ah persists across groups 1 and 3)
            uint32_t ah[4][4], bh[2][4];
#pragma unroll
            for (int i = 0; i < 4; i++)
                LDSM4(ah[i], aA + i * (16 * 80) + ks * 32);
#pragma unroll
            for (int p = 0; p < 2; p++)
                LDSM4(bh[p], aB + p * (16 * 80) + ks * 32);
#pragma unroll
            for (int i = 0; i < 4; i++)
#pragma unroll
                for (int j = 0; j < 4; j++) {
                    const int p = j >> 1, hh = (j & 1) * 2;
                    mma_bf16(acc[i][j], ah[i], bh[p][hh], bh[p][hh + 1]);
                }
            // group 2: Alo x Bhi   (al streamed one fragment at a time)
#pragma unroll
            for (int i = 0; i < 4; i++) {
                uint32_t al[4];
                LDSM4(al, aA + SUB_BYTES + i * (16 * 80) + ks * 32);
#pragma unroll
                for (int j = 0; j < 4; j++) {
                    const int p = j >> 1, hh = (j & 1) * 2;
                    mma_bf16(acc[i][j], al, bh[p][hh], bh[p][hh + 1]);
                }
            }
            // group 3: Ahi x Blo   (bl overwrites bh's registers)
            uint32_t bl[2][4];
#pragma unroll
            for (int p = 0; p < 2; p++)
                LDSM4(bl[p], aB + SUB_BYTES + p * (16 * 80) + ks * 32);
#pragma unroll
            for (int i = 0; i < 4; i++)
#pragma unroll
                for (int j = 0; j < 4; j++) {
                    const int p = j >> 1, hh = (j & 1) * 2;
                    mma_bf16(acc[i][j], ah[i], bl[p][hh], bl[p][hh + 1]);
                }
        }
        __syncthreads();
    }

    // ---- fused epilogue ----
    const long long zb = (long long)z * BH;
    const int er = lid >> 2, ec = (lid & 3) * 2;
#pragma unroll
    for (int i = 0; i < 4; i++) {
#pragma unroll
        for (int j = 0; j < 4; j++) {
            const int col = bX * 128 + wn * 32 + j * 8 + ec;
            const float2 bv = *(const float2*)(bias + z * Hv + col);
#pragma unroll
            for (int half = 0; half < 2; half++) {
                const int row = bY * 128 + wm * 64 + i * 16 + er + half * 8;
                const long long idx = zb + (long long)row * 1024 + col;
                const float c0 = acc[i][j][half * 2 + 0];
                const float c1 = acc[i][j][half * 2 + 1];
                const float2 iv = *(const float2*)(inp + idx);
                const __nv_bfloat162 hv2 = *(const __nv_bfloat162*)(Ahi + idx);
                const __nv_bfloat162 lv2 = *(const __nv_bfloat162*)(Alo + idx);
                const float hin0 = __bfloat162float(hv2.x) + __bfloat162float(lv2.x);
                const float hin1 = __bfloat162float(hv2.y) + __bfloat162float(lv2.y);
                const float pre0 = c0 + bv.x + iv.x;
                const float pre1 = c1 + bv.y + iv.y;
                if (MODE == 1) {
                    const float o0 = 0.5f * hin0 + 0.5f * tanhf(pre0);
                    const float o1 = 0.5f * hin1 + 0.5f * tanhf(pre1);
                    const __nv_bfloat16 h0 = __float2bfloat16(o0);
                    const __nv_bfloat16 h1 = __float2bfloat16(o1);
                    const __nv_bfloat16 l0 = __float2bfloat16(o0 - __bfloat162float(h0));
                    const __nv_bfloat16 l1 = __float2bfloat16(o1 - __bfloat162float(h1));
                    *(__nv_bfloat162*)(Ohi + idx) = __halves2bfloat162(h0, h1);
                    *(__nv_bfloat162*)(Olo + idx) = __halves2bfloat162(l0, l1);
                } else {
                    float2 hc = first ? make_float2(0.f, 0.f)
                                      : *(const float2*)(Hbuf + idx);
                    float2 o;
                    o.x = 0.5f * hc.x + 0.25f * hin0 + 0.25f * tanhf(pre0);
                    o.y = 0.5f * hc.y + 0.25f * hin1 + 0.25f * tanhf(pre1);
                    *(float2*)(Hbuf + idx) = o;
                }
            }
        }
    }
}

// ============================================================================
// FFMA2 SGEMM: out = A @ W^T + bias  (fp32, embed / head)
// ============================================================================
__device__ __forceinline__ unsigned long long ffma2(unsigned long long a,
                                                    unsigned long long b,
                                                    unsigned long long c) {
    unsigned long long d;
    asm("fma.rn.f32x2 %0, %1, %2, %3;" : "=l"(d) : "l"(a), "l"(b), "l"(c));
    return d;
}
__device__ __forceinline__ unsigned long long pack2(float x) {
    unsigned long long r;
    unsigned u = __float_as_uint(x);
    asm("mov.b64 %0, {%1, %1};" : "=l"(r) : "r"(u));
    return r;
}

__global__ void __launch_bounds__(256)
fgemm0(const float* __restrict__ A, const float* __restrict__ W,
       const float* __restrict__ bias, float* __restrict__ outp, int N, int K)
{
    __shared__ __align__(16) float As[2][16][128];
    __shared__ __align__(16) float Bs[2][16][128];
    const int tid = threadIdx.x;
    const int tx = tid & 15, ty = tid >> 4;
    const int lrow = tid >> 2, lcol = (tid & 3) << 2;

    const float* aP0 = A + (long long)(blockIdx.y * 128 + lrow) * K + lcol;
    const float* aP1 = aP0 + 64LL * K;
    const float* wP0 = W + (long long)(blockIdx.x * 128 + lrow) * K + lcol;
    const float* wP1 = wP0 + 64LL * K;

    float4 ra0 = *(const float4*)aP0, ra1 = *(const float4*)aP1;
    float4 rb0 = *(const float4*)wP0, rb1 = *(const float4*)wP1;
    int buf = 0;
    As[0][lcol+0][lrow]=ra0.x; As[0][lcol+1][lrow]=ra0.y; As[0][lcol+2][lrow]=ra0.z; As[0][lcol+3][lrow]=ra0.w;
    As[0][lcol+0][lrow+64]=ra1.x; As[0][lcol+1][lrow+64]=ra1.y; As[0][lcol+2][lrow+64]=ra1.z; As[0][lcol+3][lrow+64]=ra1.w;
    Bs[0][lcol+0][lrow]=rb0.x; Bs[0][lcol+1][lrow]=rb0.y; Bs[0][lcol+2][lrow]=rb0.z; Bs[0][lcol+3][lrow]=rb0.w;
    Bs[0][lcol+0][lrow+64]=rb1.x; Bs[0][lcol+1][lrow+64]=rb1.y; Bs[0][lcol+2][lrow+64]=rb1.z; Bs[0][lcol+3][lrow+64]=rb1.w;
    __syncthreads();

    unsigned long long acc[8][4];
#pragma unroll
    for (int i = 0; i < 8; i++)
#pragma unroll
        for (int j = 0; j < 4; j++) acc[i][j] = 0ULL;

    const int ktiles = K >> 4;
    for (int kt = 0; kt < ktiles; ++kt) {
        float4 na0, na1, nb0, nb1;
        const bool more = (kt + 1 < ktiles);
        if (more) {
            const int o = (kt + 1) * 16;
            na0 = *(const float4*)(aP0 + o); na1 = *(const float4*)(aP1 + o);
            nb0 = *(const float4*)(wP0 + o); nb1 = *(const float4*)(wP1 + o);
        }
#pragma unroll
        for (int k = 0; k < 16; k++) {
            float4 a0 = *(const float4*)&As[buf][k][ty * 4];
            float4 a1 = *(const float4*)&As[buf][k][64 + ty * 4];
            ulonglong2 b0 = *(const ulonglong2*)&Bs[buf][k][tx * 4];
            ulonglong2 b1 = *(const ulonglong2*)&Bs[buf][k][64 + tx * 4];
            unsigned long long bv[4] = {b0.x, b0.y, b1.x, b1.y};
            float av[8] = {a0.x, a0.y, a0.z, a0.w, a1.x, a1.y, a1.z, a1.w};
#pragma unroll
            for (int i = 0; i < 8; i++) {
                unsigned long long a2 = pack2(av[i]);
#pragma unroll
                for (int j = 0; j < 4; j++) acc[i][j] = ffma2(a2, bv[j], acc[i][j]);
            }
        }
        if (more) {
            buf ^= 1;
            As[buf][lcol+0][lrow]=na0.x; As[buf][lcol+1][lrow]=na0.y; As[buf][lcol+2][lrow]=na0.z; As[buf][lcol+3][lrow]=na0.w;
            As[buf][lcol+0][lrow+64]=na1.x; As[buf][lcol+1][lrow+64]=na1.y; As[buf][lcol+2][lrow+64]=na1.z; As[buf][lcol+3][lrow+64]=na1.w;
            Bs[buf][lcol+0][lrow]=nb0.x; Bs[buf][lcol+1][lrow]=nb0.y; Bs[buf][lcol+2][lrow]=nb0.z; Bs[buf][lcol+3][lrow]=nb0.w;
            Bs[buf][lcol+0][lrow+64]=nb1.x; Bs[buf][lcol+1][lrow+64]=nb1.y; Bs[buf][lcol+2][lrow+64]=nb1.z; Bs[buf][lcol+3][lrow+64]=nb1.w;
            __syncthreads();
        }
    }
#pragma unroll
    for (int i = 0; i < 8; i++) {
        const int row = blockIdx.y * 128 + ((i < 4) ? (ty * 4 + i) : (64 + ty * 4 + i - 4));
        const long long rbase = (long long)row * N;
#pragma unroll
        for (int p = 0; p < 4; p++) {
            const int col = blockIdx.x * 128 +
                            ((p < 2) ? (tx * 4 + p * 2) : (64 + tx * 4 + (p - 2) * 2));
            outp[rbase + col]     = __uint_as_float((unsigned)acc[i][p])         + bias[col];
            outp[rbase + col + 1] = __uint_as_float((unsigned)(acc[i][p] >> 32)) + bias[col + 1];
        }
    }
}

// ============================================================================
// Weight split: Whi/Wlo = bf16 hi/lo of block_W
// ============================================================================
__global__ void __launch_bounds__(256)
wsplit_kernel(const float* __restrict__ w)
{
    const long long e = ((long long)blockIdx.x * blockDim.x + threadIdx.x) << 2;
    const float4 v = *(const float4*)(w + e);
    __nv_bfloat16 h0 = __float2bfloat16(v.x), h1 = __float2bfloat16(v.y);
    __nv_bfloat16 h2 = __float2bfloat16(v.z), h3 = __float2bfloat16(v.w);
    __nv_bfloat16 l0 = __float2bfloat16(v.x - __bfloat162float(h0));
    __nv_bfloat16 l1 = __float2bfloat16(v.y - __bfloat162float(h1));
    __nv_bfloat16 l2 = __float2bfloat16(v.z - __bfloat162float(h2));
    __nv_bfloat16 l3 = __float2bfloat16(v.w - __bfloat162float(h3));
    ((__nv_bfloat162*)(g_Whi + e))[0] = __halves2bfloat162(h0, h1);
    ((__nv_bfloat162*)(g_Whi + e))[1] = __halves2bfloat162(h2, h3);
    ((__nv_bfloat162*)(g_Wlo + e))[0] = __halves2bfloat162(l0, l1);
    ((__nv_bfloat162*)(g_Wlo + e))[1] = __halves2bfloat162(l2, l3);
}

// ============================================================================
// Per-outer-step prep:
//   inp[n] = h[n] + (n==0 ? x_emb : h[n-1])   (h==0 on first step)
//   hi/loA = split( 0.5 * tanh(block_b[n] + inp[n]) )   (inner iter 1)
// ============================================================================
__global__ void __launch_bounds__(256)
prep_kernel(const float* __restrict__ blockb, int first)
{
    const long long e = ((long long)blockIdx.x * blockDim.x + threadIdx.x) << 2;
    const int n = (int)(e >> 20);
    const long long r = e & (BH - 1);
    const int d = (int)(e & (Hv - 1));

    float4 hv, bi;
    if (first) hv = make_float4(0.f, 0.f, 0.f, 0.f);
    else       hv = *(const float4*)&g_h[e];
    if (n == 0)      bi = *(const float4*)&g_xemb[r];
    else if (first)  bi = make_float4(0.f, 0.f, 0.f, 0.f);
    else             bi = *(const float4*)&g_h[e - BH];

    float4 v;
    v.x = hv.x + bi.x; v.y = hv.y + bi.y; v.z = hv.z + bi.z; v.w = hv.w + bi.w;
    *(float4*)&g_inp[e] = v;

    const float4 bb = *(const float4*)&blockb[n * Hv + d];
    const float t0 = 0.5f * tanhf(bb.x + v.x);
    const float t1 = 0.5f * tanhf(bb.y + v.y);
    const float t2 = 0.5f * tanhf(bb.z + v.z);
    const float t3 = 0.5f * tanhf(bb.w + v.w);
    __nv_bfloat16 h0 = __float2bfloat16(t0), h1 = __float2bfloat16(t1);
    __nv_bfloat16 h2 = __float2bfloat16(t2), h3 = __float2bfloat16(t3);
    __nv_bfloat16 l0 = __float2bfloat16(t0 - __bfloat162float(h0));
    __nv_bfloat16 l1 = __float2bfloat16(t1 - __bfloat162float(h1));
    __nv_bfloat16 l2 = __float2bfloat16(t2 - __bfloat162float(h2));
    __nv_bfloat16 l3 = __float2bfloat16(t3 - __bfloat162float(h3));
    ((__nv_bfloat162*)(g_hiA + e))[0] = __halves2bfloat162(h0, h1);
    ((__nv_bfloat162*)(g_hiA + e))[1] = __halves2bfloat162(h2, h3);
    ((__nv_bfloat162*)(g_loA + e))[0] = __halves2bfloat162(l0, l1);
    ((__nv_bfloat162*)(g_loA + e))[1] = __halves2bfloat162(l2, l3);
}

// ============================================================================
extern "C" void kernel_launch(void* const* d_in, const int* in_sizes, int n_in,
                              void* d_out, int out_size)
{
    const float* x     = (const float*)d_in[0];  // (B, DIN)
    const float* embW  = (const float*)d_in[1];  // (H, DIN)
    const float* embB  = (const float*)d_in[2];  // (H)
    const float* blkW  = (const float*)d_in[3];  // (NB, H, H)
    const float* blkB  = (const float*)d_in[4];  // (NB, H)
    const float* headW = (const float*)d_in[5];  // (DOUT, H)
    const float* headB = (const float*)d_in[6];  // (DOUT)
    float* out = (float*)d_out;                  // (B, DOUT)

    float *xemb, *h, *inp;
    __nv_bfloat16 *hiA, *loA, *hiB, *loB, *Whi, *Wlo;
    cudaGetSymbolAddress((void**)&xemb, g_xemb);
    cudaGetSymbolAddress((void**)&h,    g_h);
    cudaGetSymbolAddress((void**)&inp,  g_inp);
    cudaGetSymbolAddress((void**)&hiA,  g_hiA);
    cudaGetSymbolAddress((void**)&loA,  g_loA);
    cudaGetSymbolAddress((void**)&hiB,  g_hiB);
    cudaGetSymbolAddress((void**)&loB,  g_loB);
    cudaGetSymbolAddress((void**)&Whi,  g_Whi);
    cudaGetSymbolAddress((void**)&Wlo,  g_Wlo);

    cudaFuncSetAttribute(tgemm<1>, cudaFuncAttributeMaxDynamicSharedMemorySize, SMEM_DYN);
    cudaFuncSetAttribute(tgemm<2>, cudaFuncAttributeMaxDynamicSharedMemorySize, SMEM_DYN);

    const dim3 blk(256);

    // split weights into bf16 hi/lo (once per call)
    wsplit_kernel<<<(NBLK * Hv * Hv / 4) / 256, blk>>>(blkW);

    // embed: x_emb = x @ embW^T + embB   (M=B, N=H, K=DIN)
    fgemm0<<<dim3(Hv / 128, Bv / 128, 1), blk>>>(x, embW, embB, xemb, Hv, DIN);

    const dim3 g(Hv / 128, Bv / 128, NBLK);   // (8, 8, 10)
    const int prep_blocks = (NBLK * BH / 4) / 256;

    for (int s = 0; s < STEPS; ++s) {
        const int first = (s == 0) ? 1 : 0;
        prep_kernel<<<prep_blocks, blk>>>(blkB, first);
        // inner iterations 2..4 (ping-pong hi/lo buffers)
        tgemm<1><<<g, blk, SMEM_DYN>>>(hiA, loA, Whi, Wlo, blkB, inp, hiB, loB, nullptr, 0);
        tgemm<1><<<g, blk, SMEM_DYN>>>(hiB, loB, Whi, Wlo, blkB, inp, hiA, loA, nullptr, 0);
        tgemm<1><<<g, blk, SMEM_DYN>>>(hiA, loA, Whi, Wlo, blkB, inp, hiB, loB, nullptr, 0);
        // inner iteration 5 fused with outer update
        tgemm<2><<<g, blk, SMEM_DYN>>>(hiB, loB, Whi, Wlo, blkB, inp, nullptr, nullptr, h, first);
    }

    // head: out = h[NB-1] @ headW^T + headB   (M=B, N=DOUT, K=H)
    fgemm0<<<dim3(DOUT / 128, Bv / 128, 1), blk>>>(
        h + (long long)(NBLK - 1) * BH, headW, headB, out, DOUT, Hv);
}

// round 12
// speedup vs baseline: 2.4059x; 1.0108x over previous
#include <cuda_runtime.h>
#include <cuda_bf16.h>
#include <cstdint>
#include <math.h>

#define Bv   1024
#define DIN  512
#define Hv   1024
#define DOUT 512
#define NBLK 10
#define STEPS 30
#define BH   (Bv*Hv)   // 1<<20
#define HH   (Hv*Hv)

// -------------------- device scratch (no allocations allowed) --------------------
__device__ float g_xemb[BH];                     // 4 MB
__device__ float g_h[NBLK*BH];                   // 40 MB fp32 outer state
__device__ float g_inp[NBLK*BH];                 // 40 MB fp32 inner additive input
__device__ __nv_bfloat16 g_hiA[NBLK*BH];         // activation hi, ping
__device__ __nv_bfloat16 g_loA[NBLK*BH];         // activation lo, ping
__device__ __nv_bfloat16 g_hiB[NBLK*BH];         // pong
__device__ __nv_bfloat16 g_loB[NBLK*BH];
__device__ __nv_bfloat16 g_Whi[NBLK*HH];         // weight hi
__device__ __nv_bfloat16 g_Wlo[NBLK*HH];         // weight lo

// ============================================================================
// baseline-PTX helpers (no sm_103a-only features!)
// ============================================================================
__device__ __forceinline__ uint32_t smem_u32(const void* p) {
    uint32_t a;
    asm("{ .reg .u64 t; cvta.to.shared.u64 t, %1; cvt.u32.u64 %0, t; }"
        : "=r"(a) : "l"(p));
    return a;
}
#define CP_ASYNC16(saddr, gptr) \
    asm volatile("cp.async.cg.shared.global [%0], [%1], 16;" \
                 :: "r"(saddr), "l"(gptr) : "memory")
#define CP_COMMIT() asm volatile("cp.async.commit_group;" ::: "memory")
#define CP_WAIT(N)  asm volatile("cp.async.wait_group %0;" :: "n"(N) : "memory")

#define LDSM4(r, addr) \
    asm volatile("ldmatrix.sync.aligned.m8n8.x4.shared.b16 {%0,%1,%2,%3}, [%4];" \
                 : "=r"((r)[0]), "=r"((r)[1]), "=r"((r)[2]), "=r"((r)[3]) \
                 : "r"(addr))

__device__ __forceinline__ void mma_bf16(float* c, const uint32_t* a,
                                         uint32_t b0, uint32_t b1) {
    asm volatile("mma.sync.aligned.m16n8k16.row.col.f32.bf16.bf16.f32 "
                 "{%0,%1,%2,%3}, {%4,%5,%6,%7}, {%8,%9}, {%0,%1,%2,%3};"
                 : "+f"(c[0]), "+f"(c[1]), "+f"(c[2]), "+f"(c[3])
                 : "r"(a[0]), "r"(a[1]), "r"(a[2]), "r"(a[3]), "r"(b0), "r"(b1));
}

// ============================================================================
// CTA tile 96(M) x 128(N), BK=32, 8 warps as 2(M) x 4(N), warp tile 48x32.
// Grid (8, 11, 10) = 880 CTAs -> 99% SM-slot utilization at 2 CTAs/SM
// (vs 640/888 = 72% for the 128x128 tiling).
// Last M tile (rows 1024..1055): A loads clamped to row 1023, epilogue
// predicated on row < 1024 -> identical arithmetic on valid rows.
//
// SMEM sub-tiles per buffer (80-byte padded rows, conflict-free ldmatrix):
//   Ahi 96x80=7680 | Alo 7680 | Bhi 128x80=10240 | Blo 10240  => 35840/buffer
// ============================================================================
#define TMv   96
#define A_SUB 7680
#define B_SUB 10240
#define B_OFF (2 * A_SUB)            // 15360
#define BUF_BYTES (2 * A_SUB + 2 * B_SUB)   // 35840
#define SMEM_DYN  (2 * BUF_BYTES)           // 71680

template<int MODE>
__global__ void __launch_bounds__(256, 2)
tgemm(const __nv_bfloat16* __restrict__ Ahi, const __nv_bfloat16* __restrict__ Alo,
      const __nv_bfloat16* __restrict__ Whi, const __nv_bfloat16* __restrict__ Wlo,
      const float* __restrict__ bias, const float* __restrict__ inp,
      __nv_bfloat16* __restrict__ Ohi, __nv_bfloat16* __restrict__ Olo,
      float* __restrict__ Hbuf, int first)
{
    extern __shared__ __align__(1024) char sm[];
    const uint32_t smBase = smem_u32(sm);

    const int tid = threadIdx.x;
    const int wid = tid >> 5, lid = tid & 31;
    const int wm = wid >> 2, wn = wid & 3;       // warp grid 2(M) x 4(N)
    const int bX = blockIdx.x;                   // N tile (8)
    const int bY = blockIdx.y;                   // M tile (11)
    const int z  = blockIdx.z;

    const long long zA = (long long)z * BH;
    const long long wBase = (long long)z * HH + (long long)bX * 128 * 1024;

    // ---- ldmatrix lane base offsets (within a buffer) ----
    const uint32_t aLane = (uint32_t)((wm * 48 + (lid & 15)) * 80 + (lid >> 4) * 16);
    const int bq = lid >> 3;
    const uint32_t bLane = (uint32_t)(B_OFF +
                          (wn * 32 + ((bq >> 1) * 8) + (lid & 7)) * 80 + (bq & 1) * 16);

    float acc[3][4][4];
#pragma unroll
    for (int i = 0; i < 3; i++)
#pragma unroll
        for (int j = 0; j < 4; j++)
#pragma unroll
            for (int q = 0; q < 4; q++) acc[i][j][q] = 0.f;

    // ---- tile loader: 3 A-chunks + 4 B-chunks of 16B per thread ----
    auto issue_loads = [&](int kt, int buf) {
        const uint32_t sBuf = smBase + buf * BUF_BYTES;
        const int kb = kt * 32;
#pragma unroll
        for (int t = 0; t < 3; t++) {            // A: 768 chunks (hi 384 | lo 384)
            const int idx = t * 256 + tid;
            const int sub = (idx >= 384) ? 1 : 0;
            const int rem = idx - sub * 384;
            const int row = rem >> 2, chk = rem & 3;
            int grow = bY * TMv + row;
            if (grow > Bv - 1) grow = Bv - 1;    // clamp OOB rows (last M tile)
            const __nv_bfloat16* g = (sub ? Alo : Ahi) + zA
                                   + (long long)grow * 1024 + kb + chk * 8;
            CP_ASYNC16(sBuf + sub * A_SUB + row * 80 + chk * 16, g);
        }
#pragma unroll
        for (int t = 0; t < 4; t++) {            // B: 1024 chunks (hi 512 | lo 512)
            const int idx = t * 256 + tid;
            const int sub = (idx >= 512) ? 1 : 0;
            const int rem = idx - sub * 512;
            const int row = rem >> 2, chk = rem & 3;
            const __nv_bfloat16* g = (sub ? Wlo : Whi) + wBase
                                   + (long long)row * 1024 + kb + chk * 8;
            CP_ASYNC16(sBuf + B_OFF + sub * B_SUB + row * 80 + chk * 16, g);
        }
        CP_COMMIT();
    };

    issue_loads(0, 0);

    for (int kt = 0; kt < 32; kt++) {
        const int buf = kt & 1;
        if (kt + 1 < 32) {
            issue_loads(kt + 1, buf ^ 1);
            CP_WAIT(1);
        } else {
            CP_WAIT(0);
        }
        __syncthreads();

        const uint32_t sBuf = smBase + buf * BUF_BYTES;
        const uint32_t aA = sBuf + aLane;
        const uint32_t aB = sBuf + bLane;
#pragma unroll
        for (int ks = 0; ks < 2; ks++) {
            // group 1: Ahi x Bhi  (ah persists to group 3)
            uint32_t ah[3][4], bh[2][4];
#pragma unroll
            for (int i = 0; i < 3; i++)
                LDSM4(ah[i], aA + i * (16 * 80) + ks * 32);
#pragma unroll
            for (int p = 0; p < 2; p++)
                LDSM4(bh[p], aB + p * (16 * 80) + ks * 32);
#pragma unroll
            for (int i = 0; i < 3; i++)
#pragma unroll
                for (int j = 0; j < 4; j++) {
                    const int p = j >> 1, hh = (j & 1) * 2;
                    mma_bf16(acc[i][j], ah[i], bh[p][hh], bh[p][hh + 1]);
                }
            // group 2: Alo x Bhi  (al streamed one fragment at a time)
#pragma unroll
            for (int i = 0; i < 3; i++) {
                uint32_t al[4];
                LDSM4(al, aA + A_SUB + i * (16 * 80) + ks * 32);
#pragma unroll
                for (int j = 0; j < 4; j++) {
                    const int p = j >> 1, hh = (j & 1) * 2;
                    mma_bf16(acc[i][j], al, bh[p][hh], bh[p][hh + 1]);
                }
            }
            // group 3: Ahi x Blo  (bl overwrites bh's registers)
            uint32_t bl[2][4];
#pragma unroll
            for (int p = 0; p < 2; p++)
                LDSM4(bl[p], aB + B_SUB + p * (16 * 80) + ks * 32);
#pragma unroll
            for (int i = 0; i < 3; i++)
#pragma unroll
                for (int j = 0; j < 4; j++) {
                    const int p = j >> 1, hh = (j & 1) * 2;
                    mma_bf16(acc[i][j], ah[i], bl[p][hh], bl[p][hh + 1]);
                }
        }
        __syncthreads();
    }

    // ---- fused epilogue (predicated on row < Bv for the partial M tile) ----
    const int er = lid >> 2, ec = (lid & 3) * 2;
#pragma unroll
    for (int i = 0; i < 3; i++) {
#pragma unroll
        for (int j = 0; j < 4; j++) {
            const int col = bX * 128 + wn * 32 + j * 8 + ec;
            const float2 bv = *(const float2*)(bias + z * Hv + col);
#pragma unroll
            for (int half = 0; half < 2; half++) {
                const int row = bY * TMv + wm * 48 + i * 16 + er + half * 8;
                if (row >= Bv) continue;
                const long long idx = zA + (long long)row * 1024 + col;
                const float c0 = acc[i][j][half * 2 + 0];
                const float c1 = acc[i][j][half * 2 + 1];
                const float2 iv = *(const float2*)(inp + idx);
                const __nv_bfloat162 hv2 = *(const __nv_bfloat162*)(Ahi + idx);
                const __nv_bfloat162 lv2 = *(const __nv_bfloat162*)(Alo + idx);
                const float hin0 = __bfloat162float(hv2.x) + __bfloat162float(lv2.x);
                const float hin1 = __bfloat162float(hv2.y) + __bfloat162float(lv2.y);
                const float pre0 = c0 + bv.x + iv.x;
                const float pre1 = c1 + bv.y + iv.y;
                if (MODE == 1) {
                    const float o0 = 0.5f * hin0 + 0.5f * tanhf(pre0);
                    const float o1 = 0.5f * hin1 + 0.5f * tanhf(pre1);
                    const __nv_bfloat16 h0 = __float2bfloat16(o0);
                    const __nv_bfloat16 h1 = __float2bfloat16(o1);
                    const __nv_bfloat16 l0 = __float2bfloat16(o0 - __bfloat162float(h0));
                    const __nv_bfloat16 l1 = __float2bfloat16(o1 - __bfloat162float(h1));
                    *(__nv_bfloat162*)(Ohi + idx) = __halves2bfloat162(h0, h1);
                    *(__nv_bfloat162*)(Olo + idx) = __halves2bfloat162(l0, l1);
                } else {
                    float2 hc = first ? make_float2(0.f, 0.f)
                                      : *(const float2*)(Hbuf + idx);
                    float2 o;
                    o.x = 0.5f * hc.x + 0.25f * hin0 + 0.25f * tanhf(pre0);
                    o.y = 0.5f * hc.y + 0.25f * hin1 + 0.25f * tanhf(pre1);
                    *(float2*)(Hbuf + idx) = o;
                }
            }
        }
    }
}

// ============================================================================
// FFMA2 SGEMM: out = A @ W^T + bias  (fp32, embed / head)
// ============================================================================
__device__ __forceinline__ unsigned long long ffma2(unsigned long long a,
                                                    unsigned long long b,
                                                    unsigned long long c) {
    unsigned long long d;
    asm("fma.rn.f32x2 %0, %1, %2, %3;" : "=l"(d) : "l"(a), "l"(b), "l"(c));
    return d;
}
__device__ __forceinline__ unsigned long long pack2(float x) {
    unsigned long long r;
    unsigned u = __float_as_uint(x);
    asm("mov.b64 %0, {%1, %1};" : "=l"(r) : "r"(u));
    return r;
}

__global__ void __launch_bounds__(256)
fgemm0(const float* __restrict__ A, const float* __restrict__ W,
       const float* __restrict__ bias, float* __restrict__ outp, int N, int K)
{
    __shared__ __align__(16) float As[2][16][128];
    __shared__ __align__(16) float Bs[2][16][128];
    const int tid = threadIdx.x;
    const int tx = tid & 15, ty = tid >> 4;
    const int lrow = tid >> 2, lcol = (tid & 3) << 2;

    const float* aP0 = A + (long long)(blockIdx.y * 128 + lrow) * K + lcol;
    const float* aP1 = aP0 + 64LL * K;
    const float* wP0 = W + (long long)(blockIdx.x * 128 + lrow) * K + lcol;
    const float* wP1 = wP0 + 64LL * K;

    float4 ra0 = *(const float4*)aP0, ra1 = *(const float4*)aP1;
    float4 rb0 = *(const float4*)wP0, rb1 = *(const float4*)wP1;
    int buf = 0;
    As[0][lcol+0][lrow]=ra0.x; As[0][lcol+1][lrow]=ra0.y; As[0][lcol+2][lrow]=ra0.z; As[0][lcol+3][lrow]=ra0.w;
    As[0][lcol+0][lrow+64]=ra1.x; As[0][lcol+1][lrow+64]=ra1.y; As[0][lcol+2][lrow+64]=ra1.z; As[0][lcol+3][lrow+64]=ra1.w;
    Bs[0][lcol+0][lrow]=rb0.x; Bs[0][lcol+1][lrow]=rb0.y; Bs[0][lcol+2][lrow]=rb0.z; Bs[0][lcol+3][lrow]=rb0.w;
    Bs[0][lcol+0][lrow+64]=rb1.x; Bs[0][lcol+1][lrow+64]=rb1.y; Bs[0][lcol+2][lrow+64]=rb1.z; Bs[0][lcol+3][lrow+64]=rb1.w;
    __syncthreads();

    unsigned long long acc[8][4];
#pragma unroll
    for (int i = 0; i < 8; i++)
#pragma unroll
        for (int j = 0; j < 4; j++) acc[i][j] = 0ULL;

    const int ktiles = K >> 4;
    for (int kt = 0; kt < ktiles; ++kt) {
        float4 na0, na1, nb0, nb1;
        const bool more = (kt + 1 < ktiles);
        if (more) {
            const int o = (kt + 1) * 16;
            na0 = *(const float4*)(aP0 + o); na1 = *(const float4*)(aP1 + o);
            nb0 = *(const float4*)(wP0 + o); nb1 = *(const float4*)(wP1 + o);
        }
#pragma unroll
        for (int k = 0; k < 16; k++) {
            float4 a0 = *(const float4*)&As[buf][k][ty * 4];
            float4 a1 = *(const float4*)&As[buf][k][64 + ty * 4];
            ulonglong2 b0 = *(const ulonglong2*)&Bs[buf][k][tx * 4];
            ulonglong2 b1 = *(const ulonglong2*)&Bs[buf][k][64 + tx * 4];
            unsigned long long bv[4] = {b0.x, b0.y, b1.x, b1.y};
            float av[8] = {a0.x, a0.y, a0.z, a0.w, a1.x, a1.y, a1.z, a1.w};
#pragma unroll
            for (int i = 0; i < 8; i++) {
                unsigned long long a2 = pack2(av[i]);
#pragma unroll
                for (int j = 0; j < 4; j++) acc[i][j] = ffma2(a2, bv[j], acc[i][j]);
            }
        }
        if (more) {
            buf ^= 1;
            As[buf][lcol+0][lrow]=na0.x; As[buf][lcol+1][lrow]=na0.y; As[buf][lcol+2][lrow]=na0.z; As[buf][lcol+3][lrow]=na0.w;
            As[buf][lcol+0][lrow+64]=na1.x; As[buf][lcol+1][lrow+64]=na1.y; As[buf][lcol+2][lrow+64]=na1.z; As[buf][lcol+3][lrow+64]=na1.w;
            Bs[buf][lcol+0][lrow]=nb0.x; Bs[buf][lcol+1][lrow]=nb0.y; Bs[buf][lcol+2][lrow]=nb0.z; Bs[buf][lcol+3][lrow]=nb0.w;
            Bs[buf][lcol+0][lrow+64]=nb1.x; Bs[buf][lcol+1][lrow+64]=nb1.y; Bs[buf][lcol+2][lrow+64]=nb1.z; Bs[buf][lcol+3][lrow+64]=nb1.w;
            __syncthreads();
        }
    }
#pragma unroll
    for (int i = 0; i < 8; i++) {
        const int row = blockIdx.y * 128 + ((i < 4) ? (ty * 4 + i) : (64 + ty * 4 + i - 4));
        const long long rbase = (long long)row * N;
#pragma unroll
        for (int p = 0; p < 4; p++) {
            const int col = blockIdx.x * 128 +
                            ((p < 2) ? (tx * 4 + p * 2) : (64 + tx * 4 + (p - 2) * 2));
            outp[rbase + col]     = __uint_as_float((unsigned)acc[i][p])         + bias[col];
            outp[rbase + col + 1] = __uint_as_float((unsigned)(acc[i][p] >> 32)) + bias[col + 1];
        }
    }
}

// ============================================================================
// Weight split: Whi/Wlo = bf16 hi/lo of block_W
// ============================================================================
__global__ void __launch_bounds__(256)
wsplit_kernel(const float* __restrict__ w)
{
    const long long e = ((long long)blockIdx.x * blockDim.x + threadIdx.x) << 2;
    const float4 v = *(const float4*)(w + e);
    __nv_bfloat16 h0 = __float2bfloat16(v.x), h1 = __float2bfloat16(v.y);
    __nv_bfloat16 h2 = __float2bfloat16(v.z), h3 = __float2bfloat16(v.w);
    __nv_bfloat16 l0 = __float2bfloat16(v.x - __bfloat162float(h0));
    __nv_bfloat16 l1 = __float2bfloat16(v.y - __bfloat162float(h1));
    __nv_bfloat16 l2 = __float2bfloat16(v.z - __bfloat162float(h2));
    __nv_bfloat16 l3 = __float2bfloat16(v.w - __bfloat162float(h3));
    ((__nv_bfloat162*)(g_Whi + e))[0] = __halves2bfloat162(h0, h1);
    ((__nv_bfloat162*)(g_Whi + e))[1] = __halves2bfloat162(h2, h3);
    ((__nv_bfloat162*)(g_Wlo + e))[0] = __halves2bfloat162(l0, l1);
    ((__nv_bfloat162*)(g_Wlo + e))[1] = __halves2bfloat162(l2, l3);
}

// ============================================================================
// Per-outer-step prep:
//   inp[n] = h[n] + (n==0 ? x_emb : h[n-1])   (h==0 on first step)
//   hi/loA = split( 0.5 * tanh(block_b[n] + inp[n]) )   (inner iter 1)
// ============================================================================
__global__ void __launch_bounds__(256)
prep_kernel(const float* __restrict__ blockb, int first)
{
    const long long e = ((long long)blockIdx.x * blockDim.x + threadIdx.x) << 2;
    const int n = (int)(e >> 20);
    const long long r = e & (BH - 1);
    const int d = (int)(e & (Hv - 1));

    float4 hv, bi;
    if (first) hv = make_float4(0.f, 0.f, 0.f, 0.f);
    else       hv = *(const float4*)&g_h[e];
    if (n == 0)      bi = *(const float4*)&g_xemb[r];
    else if (first)  bi = make_float4(0.f, 0.f, 0.f, 0.f);
    else             bi = *(const float4*)&g_h[e - BH];

    float4 v;
    v.x = hv.x + bi.x; v.y = hv.y + bi.y; v.z = hv.z + bi.z; v.w = hv.w + bi.w;
    *(float4*)&g_inp[e] = v;

    const float4 bb = *(const float4*)&blockb[n * Hv + d];
    const float t0 = 0.5f * tanhf(bb.x + v.x);
    const float t1 = 0.5f * tanhf(bb.y + v.y);
    const float t2 = 0.5f * tanhf(bb.z + v.z);
    const float t3 = 0.5f * tanhf(bb.w + v.w);
    __nv_bfloat16 h0 = __float2bfloat16(t0), h1 = __float2bfloat16(t1);
    __nv_bfloat16 h2 = __float2bfloat16(t2), h3 = __float2bfloat16(t3);
    __nv_bfloat16 l0 = __float2bfloat16(t0 - __bfloat162float(h0));
    __nv_bfloat16 l1 = __float2bfloat16(t1 - __bfloat162float(h1));
    __nv_bfloat16 l2 = __float2bfloat16(t2 - __bfloat162float(h2));
    __nv_bfloat16 l3 = __float2bfloat16(t3 - __bfloat162float(h3));
    ((__nv_bfloat162*)(g_hiA + e))[0] = __halves2bfloat162(h0, h1);
    ((__nv_bfloat162*)(g_hiA + e))[1] = __halves2bfloat162(h2, h3);
    ((__nv_bfloat162*)(g_loA + e))[0] = __halves2bfloat162(l0, l1);
    ((__nv_bfloat162*)(g_loA + e))[1] = __halves2bfloat162(l2, l3);
}

// ============================================================================
extern "C" void kernel_launch(void* const* d_in, const int* in_sizes, int n_in,
                              void* d_out, int out_size)
{
    const float* x     = (const float*)d_in[0];  // (B, DIN)
    const float* embW  = (const float*)d_in[1];  // (H, DIN)
    const float* embB  = (const float*)d_in[2];  // (H)
    const float* blkW  = (const float*)d_in[3];  // (NB, H, H)
    const float* blkB  = (const float*)d_in[4];  // (NB, H)
    const float* headW = (const float*)d_in[5];  // (DOUT, H)
    const float* headB = (const float*)d_in[6];  // (DOUT)
    float* out = (float*)d_out;                  // (B, DOUT)

    float *xemb, *h, *inp;
    __nv_bfloat16 *hiA, *loA, *hiB, *loB, *Whi, *Wlo;
    cudaGetSymbolAddress((void**)&xemb, g_xemb);
    cudaGetSymbolAddress((void**)&h,    g_h);
    cudaGetSymbolAddress((void**)&inp,  g_inp);
    cudaGetSymbolAddress((void**)&hiA,  g_hiA);
    cudaGetSymbolAddress((void**)&loA,  g_loA);
    cudaGetSymbolAddress((void**)&hiB,  g_hiB);
    cudaGetSymbolAddress((void**)&loB,  g_loB);
    cudaGetSymbolAddress((void**)&Whi,  g_Whi);
    cudaGetSymbolAddress((void**)&Wlo,  g_Wlo);

    cudaFuncSetAttribute(tgemm<1>, cudaFuncAttributeMaxDynamicSharedMemorySize, SMEM_DYN);
    cudaFuncSetAttribute(tgemm<2>, cudaFuncAttributeMaxDynamicSharedMemorySize, SMEM_DYN);

    const dim3 blk(256);

    // split weights into bf16 hi/lo (once per call)
    wsplit_kernel<<<(NBLK * HH / 4) / 256, blk>>>(blkW);

    // embed: x_emb = x @ embW^T + embB   (M=B, N=H, K=DIN)
    fgemm0<<<dim3(Hv / 128, Bv / 128, 1), blk>>>(x, embW, embB, xemb, Hv, DIN);

    const dim3 g(Hv / 128, (Bv + TMv - 1) / TMv, NBLK);   // (8, 11, 10) = 880 CTAs
    const int prep_blocks = (NBLK * BH / 4) / 256;

    for (int s = 0; s < STEPS; ++s) {
        const int first = (s == 0) ? 1 : 0;
        prep_kernel<<<prep_blocks, blk>>>(blkB, first);
        // inner iterations 2..4 (ping-pong hi/lo buffers)
        tgemm<1><<<g, blk, SMEM_DYN>>>(hiA, loA, Whi, Wlo, blkB, inp, hiB, loB, nullptr, 0);
        tgemm<1><<<g, blk, SMEM_DYN>>>(hiB, loB, Whi, Wlo, blkB, inp, hiA, loA, nullptr, 0);
        tgemm<1><<<g, blk, SMEM_DYN>>>(hiA, loA, Whi, Wlo, blkB, inp, hiB, loB, nullptr, 0);
        // inner iteration 5 fused with outer update
        tgemm<2><<<g, blk, SMEM_DYN>>>(hiB, loB, Whi, Wlo, blkB, inp, nullptr, nullptr, h, first);
    }

    // head: out = h[NB-1] @ headW^T + headB   (M=B, N=DOUT, K=H)
    fgemm0<<<dim3(DOUT / 128, Bv / 128, 1), blk>>>(
        h + (long long)(NBLK - 1) * BH, headW, headB, out, DOUT, Hv);
}

// round 13
// speedup vs baseline: 2.5174x; 1.0464x over previous
#include <cuda_runtime.h>
#include <cuda_bf16.h>
#include <cstdint>
#include <math.h>

#define Bv   1024
#define DIN  512
#define Hv   1024
#define DOUT 512
#define NBLK 10
#define STEPS 30
#define BH   (Bv*Hv)   // 1<<20
#define HH   (Hv*Hv)

// -------------------- device scratch (no allocations allowed) --------------------
__device__ float g_xemb[BH];                     // 4 MB
__device__ float g_h[NBLK*BH];                   // 40 MB fp32 outer state
__device__ float g_inp[NBLK*BH];                 // 40 MB fp32 inner additive input
__device__ __nv_bfloat16 g_hiA[NBLK*BH];         // activation hi, ping
__device__ __nv_bfloat16 g_loA[NBLK*BH];         // activation lo, ping
__device__ __nv_bfloat16 g_hiB[NBLK*BH];         // pong
__device__ __nv_bfloat16 g_loB[NBLK*BH];
__device__ __nv_bfloat16 g_Whi[NBLK*HH];         // weight hi
__device__ __nv_bfloat16 g_Wlo[NBLK*HH];         // weight lo

// ============================================================================
// baseline-PTX helpers (no sm_103a-only features!)
// ============================================================================
__device__ __forceinline__ uint32_t smem_u32(const void* p) {
    uint32_t a;
    asm("{ .reg .u64 t; cvta.to.shared.u64 t, %1; cvt.u32.u64 %0, t; }"
        : "=r"(a) : "l"(p));
    return a;
}
#define CP_ASYNC16(saddr, gptr) \
    asm volatile("cp.async.cg.shared.global [%0], [%1], 16;" \
                 :: "r"(saddr), "l"(gptr) : "memory")
#define CP_COMMIT() asm volatile("cp.async.commit_group;" ::: "memory")
#define CP_WAIT(N)  asm volatile("cp.async.wait_group %0;" :: "n"(N) : "memory")

#define LDSM4(r, addr) \
    asm volatile("ldmatrix.sync.aligned.m8n8.x4.shared.b16 {%0,%1,%2,%3}, [%4];" \
                 : "=r"((r)[0]), "=r"((r)[1]), "=r"((r)[2]), "=r"((r)[3]) \
                 : "r"(addr))

__device__ __forceinline__ void mma_bf16(float* c, const uint32_t* a,
                                         uint32_t b0, uint32_t b1) {
    asm volatile("mma.sync.aligned.m16n8k16.row.col.f32.bf16.bf16.f32 "
                 "{%0,%1,%2,%3}, {%4,%5,%6,%7}, {%8,%9}, {%0,%1,%2,%3};"
                 : "+f"(c[0]), "+f"(c[1]), "+f"(c[2]), "+f"(c[3])
                 : "r"(a[0]), "r"(a[1]), "r"(a[2]), "r"(a[3]), "r"(b0), "r"(b1));
}

// ============================================================================
// CTA tile 96(M) x 128(N), BK=32, 8 warps as 2(M) x 4(N), warp tile 48x32.
// 3-stage cp.async pipeline, ONE __syncthreads per ktile:
//   at ktile kt: CP_WAIT ensures group kt landed; the barrier also proves all
//   warps finished computing ktile kt-1 (which used buffer (kt+2)%3), so loads
//   for kt+2 can be issued into that buffer right after the barrier.
// 2 CTAs/SM: smem 3*35840 = 107,520 B/CTA -> 210 KB/SM (fits 228 KB).
// Last M tile (rows 1024..1055): A loads clamped, epilogue predicated.
//
// SMEM sub-tiles per buffer (80-byte padded rows, conflict-free ldmatrix):
//   Ahi 96x80=7680 | Alo 7680 | Bhi 128x80=10240 | Blo 10240  => 35840/buffer
// ============================================================================
#define TMv   96
#define A_SUB 7680
#define B_SUB 10240
#define B_OFF (2 * A_SUB)            // 15360
#define BUF_BYTES (2 * A_SUB + 2 * B_SUB)   // 35840
#define NSTAGE 3
#define SMEM_DYN  (NSTAGE * BUF_BYTES)      // 107520

template<int MODE>
__global__ void __launch_bounds__(256, 2)
tgemm(const __nv_bfloat16* __restrict__ Ahi, const __nv_bfloat16* __restrict__ Alo,
      const __nv_bfloat16* __restrict__ Whi, const __nv_bfloat16* __restrict__ Wlo,
      const float* __restrict__ bias, const float* __restrict__ inp,
      __nv_bfloat16* __restrict__ Ohi, __nv_bfloat16* __restrict__ Olo,
      float* __restrict__ Hbuf, int first)
{
    extern __shared__ __align__(1024) char sm[];
    const uint32_t smBase = smem_u32(sm);

    const int tid = threadIdx.x;
    const int wid = tid >> 5, lid = tid & 31;
    const int wm = wid >> 2, wn = wid & 3;       // warp grid 2(M) x 4(N)
    const int bX = blockIdx.x;                   // N tile (8)
    const int bY = blockIdx.y;                   // M tile (11)
    const int z  = blockIdx.z;

    const long long zA = (long long)z * BH;
    const long long wBase = (long long)z * HH + (long long)bX * 128 * 1024;

    // ---- ldmatrix lane base offsets (within a buffer) ----
    const uint32_t aLane = (uint32_t)((wm * 48 + (lid & 15)) * 80 + (lid >> 4) * 16);
    const int bq = lid >> 3;
    const uint32_t bLane = (uint32_t)(B_OFF +
                          (wn * 32 + ((bq >> 1) * 8) + (lid & 7)) * 80 + (bq & 1) * 16);

    float acc[3][4][4];
#pragma unroll
    for (int i = 0; i < 3; i++)
#pragma unroll
        for (int j = 0; j < 4; j++)
#pragma unroll
            for (int q = 0; q < 4; q++) acc[i][j][q] = 0.f;

    // ---- tile loader: 3 A-chunks + 4 B-chunks of 16B per thread ----
    auto issue_loads = [&](int kt, int buf) {
        const uint32_t sBuf = smBase + buf * BUF_BYTES;
        const int kb = kt * 32;
#pragma unroll
        for (int t = 0; t < 3; t++) {            // A: 768 chunks (hi 384 | lo 384)
            const int idx = t * 256 + tid;
            const int sub = (idx >= 384) ? 1 : 0;
            const int rem = idx - sub * 384;
            const int row = rem >> 2, chk = rem & 3;
            int grow = bY * TMv + row;
            if (grow > Bv - 1) grow = Bv - 1;    // clamp OOB rows (last M tile)
            const __nv_bfloat16* g = (sub ? Alo : Ahi) + zA
                                   + (long long)grow * 1024 + kb + chk * 8;
            CP_ASYNC16(sBuf + sub * A_SUB + row * 80 + chk * 16, g);
        }
#pragma unroll
        for (int t = 0; t < 4; t++) {            // B: 1024 chunks (hi 512 | lo 512)
            const int idx = t * 256 + tid;
            const int sub = (idx >= 512) ? 1 : 0;
            const int rem = idx - sub * 512;
            const int row = rem >> 2, chk = rem & 3;
            const __nv_bfloat16* g = (sub ? Wlo : Whi) + wBase
                                   + (long long)row * 1024 + kb + chk * 8;
            CP_ASYNC16(sBuf + B_OFF + sub * B_SUB + row * 80 + chk * 16, g);
        }
        CP_COMMIT();
    };

    // prologue: 2 groups in flight
    issue_loads(0, 0);
    issue_loads(1, 1);

    int buf = 0;
    for (int kt = 0; kt < 32; kt++) {
        if (kt < 31) { CP_WAIT(1); }   // group kt complete (one still flying)
        else         { CP_WAIT(0); }   // final tile: drain everything
        __syncthreads();               // also proves compute(kt-1) done by all
        if (kt + 2 < 32) {
            int nb = buf + 2; if (nb >= NSTAGE) nb -= NSTAGE;
            issue_loads(kt + 2, nb);   // safe: buffer (kt+2)%3 freed at barrier
        }

        const uint32_t sBuf = smBase + buf * BUF_BYTES;
        const uint32_t aA = sBuf + aLane;
        const uint32_t aB = sBuf + bLane;
#pragma unroll
        for (int ks = 0; ks < 2; ks++) {
            // group 1: Ahi x Bhi  (ah persists to group 3)
            uint32_t ah[3][4], bh[2][4];
#pragma unroll
            for (int i = 0; i < 3; i++)
                LDSM4(ah[i], aA + i * (16 * 80) + ks * 32);
#pragma unroll
            for (int p = 0; p < 2; p++)
                LDSM4(bh[p], aB + p * (16 * 80) + ks * 32);
#pragma unroll
            for (int i = 0; i < 3; i++)
#pragma unroll
                for (int j = 0; j < 4; j++) {
                    const int p = j >> 1, hh = (j & 1) * 2;
                    mma_bf16(acc[i][j], ah[i], bh[p][hh], bh[p][hh + 1]);
                }
            // group 2: Alo x Bhi  (al streamed one fragment at a time)
#pragma unroll
            for (int i = 0; i < 3; i++) {
                uint32_t al[4];
                LDSM4(al, aA + A_SUB + i * (16 * 80) + ks * 32);
#pragma unroll
                for (int j = 0; j < 4; j++) {
                    const int p = j >> 1, hh = (j & 1) * 2;
                    mma_bf16(acc[i][j], al, bh[p][hh], bh[p][hh + 1]);
                }
            }
            // group 3: Ahi x Blo  (bl overwrites bh's registers)
            uint32_t bl[2][4];
#pragma unroll
            for (int p = 0; p < 2; p++)
                LDSM4(bl[p], aB + B_SUB + p * (16 * 80) + ks * 32);
#pragma unroll
            for (int i = 0; i < 3; i++)
#pragma unroll
                for (int j = 0; j < 4; j++) {
                    const int p = j >> 1, hh = (j & 1) * 2;
                    mma_bf16(acc[i][j], ah[i], bl[p][hh], bl[p][hh + 1]);
                }
        }
        buf++; if (buf >= NSTAGE) buf = 0;
    }

    // ---- fused epilogue (predicated on row < Bv for the partial M tile) ----
    const int er = lid >> 2, ec = (lid & 3) * 2;
#pragma unroll
    for (int i = 0; i < 3; i++) {
#pragma unroll
        for (int j = 0; j < 4; j++) {
            const int col = bX * 128 + wn * 32 + j * 8 + ec;
            const float2 bv = *(const float2*)(bias + z * Hv + col);
#pragma unroll
            for (int half = 0; half < 2; half++) {
                const int row = bY * TMv + wm * 48 + i * 16 + er + half * 8;
                if (row >= Bv) continue;
                const long long idx = zA + (long long)row * 1024 + col;
                const float c0 = acc[i][j][half * 2 + 0];
                const float c1 = acc[i][j][half * 2 + 1];
                const float2 iv = *(const float2*)(inp + idx);
                const __nv_bfloat162 hv2 = *(const __nv_bfloat162*)(Ahi + idx);
                const __nv_bfloat162 lv2 = *(const __nv_bfloat162*)(Alo + idx);
                const float hin0 = __bfloat162float(hv2.x) + __bfloat162float(lv2.x);
                const float hin1 = __bfloat162float(hv2.y) + __bfloat162float(lv2.y);
                const float pre0 = c0 + bv.x + iv.x;
                const float pre1 = c1 + bv.y + iv.y;
                if (MODE == 1) {
                    const float o0 = 0.5f * hin0 + 0.5f * tanhf(pre0);
                    const float o1 = 0.5f * hin1 + 0.5f * tanhf(pre1);
                    const __nv_bfloat16 h0 = __float2bfloat16(o0);
                    const __nv_bfloat16 h1 = __float2bfloat16(o1);
                    const __nv_bfloat16 l0 = __float2bfloat16(o0 - __bfloat162float(h0));
                    const __nv_bfloat16 l1 = __float2bfloat16(o1 - __bfloat162float(h1));
                    *(__nv_bfloat162*)(Ohi + idx) = __halves2bfloat162(h0, h1);
                    *(__nv_bfloat162*)(Olo + idx) = __halves2bfloat162(l0, l1);
                } else {
                    float2 hc = first ? make_float2(0.f, 0.f)
                                      : *(const float2*)(Hbuf + idx);
                    float2 o;
                    o.x = 0.5f * hc.x + 0.25f * hin0 + 0.25f * tanhf(pre0);
                    o.y = 0.5f * hc.y + 0.25f * hin1 + 0.25f * tanhf(pre1);
                    *(float2*)(Hbuf + idx) = o;
                }
            }
        }
    }
}

// ============================================================================
// FFMA2 SGEMM: out = A @ W^T + bias  (fp32, embed / head)
// ============================================================================
__device__ __forceinline__ unsigned long long ffma2(unsigned long long a,
                                                    unsigned long long b,
                                                    unsigned long long c) {
    unsigned long long d;
    asm("fma.rn.f32x2 %0, %1, %2, %3;" : "=l"(d) : "l"(a), "l"(b), "l"(c));
    return d;
}
__device__ __forceinline__ unsigned long long pack2(float x) {
    unsigned long long r;
    unsigned u = __float_as_uint(x);
    asm("mov.b64 %0, {%1, %1};" : "=l"(r) : "r"(u));
    return r;
}

__global__ void __launch_bounds__(256)
fgemm0(const float* __restrict__ A, const float* __restrict__ W,
       const float* __restrict__ bias, float* __restrict__ outp, int N, int K)
{
    __shared__ __align__(16) float As[2][16][128];
    __shared__ __align__(16) float Bs[2][16][128];
    const int tid = threadIdx.x;
    const int tx = tid & 15, ty = tid >> 4;
    const int lrow = tid >> 2, lcol = (tid & 3) << 2;

    const float* aP0 = A + (long long)(blockIdx.y * 128 + lrow) * K + lcol;
    const float* aP1 = aP0 + 64LL * K;
    const float* wP0 = W + (long long)(blockIdx.x * 128 + lrow) * K + lcol;
    const float* wP1 = wP0 + 64LL * K;

    float4 ra0 = *(const float4*)aP0, ra1 = *(const float4*)aP1;
    float4 rb0 = *(const float4*)wP0, rb1 = *(const float4*)wP1;
    int buf = 0;
    As[0][lcol+0][lrow]=ra0.x; As[0][lcol+1][lrow]=ra0.y; As[0][lcol+2][lrow]=ra0.z; As[0][lcol+3][lrow]=ra0.w;
    As[0][lcol+0][lrow+64]=ra1.x; As[0][lcol+1][lrow+64]=ra1.y; As[0][lcol+2][lrow+64]=ra1.z; As[0][lcol+3][lrow+64]=ra1.w;
    Bs[0][lcol+0][lrow]=rb0.x; Bs[0][lcol+1][lrow]=rb0.y; Bs[0][lcol+2][lrow]=rb0.z; Bs[0][lcol+3][lrow]=rb0.w;
    Bs[0][lcol+0][lrow+64]=rb1.x; Bs[0][lcol+1][lrow+64]=rb1.y; Bs[0][lcol+2][lrow+64]=rb1.z; Bs[0][lcol+3][lrow+64]=rb1.w;
    __syncthreads();

    unsigned long long acc[8][4];
#pragma unroll
    for (int i = 0; i < 8; i++)
#pragma unroll
        for (int j = 0; j < 4; j++) acc[i][j] = 0ULL;

    const int ktiles = K >> 4;
    for (int kt = 0; kt < ktiles; ++kt) {
        float4 na0, na1, nb0, nb1;
        const bool more = (kt + 1 < ktiles);
        if (more) {
            const int o = (kt + 1) * 16;
            na0 = *(const float4*)(aP0 + o); na1 = *(const float4*)(aP1 + o);
            nb0 = *(const float4*)(wP0 + o); nb1 = *(const float4*)(wP1 + o);
        }
#pragma unroll
        for (int k = 0; k < 16; k++) {
            float4 a0 = *(const float4*)&As[buf][k][ty * 4];
            float4 a1 = *(const float4*)&As[buf][k][64 + ty * 4];
            ulonglong2 b0 = *(const ulonglong2*)&Bs[buf][k][tx * 4];
            ulonglong2 b1 = *(const ulonglong2*)&Bs[buf][k][64 + tx * 4];
            unsigned long long bv[4] = {b0.x, b0.y, b1.x, b1.y};
            float av[8] = {a0.x, a0.y, a0.z, a0.w, a1.x, a1.y, a1.z, a1.w};
#pragma unroll
            for (int i = 0; i < 8; i++) {
                unsigned long long a2 = pack2(av[i]);
#pragma unroll
                for (int j = 0; j < 4; j++) acc[i][j] = ffma2(a2, bv[j], acc[i][j]);
            }
        }
        if (more) {
            buf ^= 1;
            As[buf][lcol+0][lrow]=na0.x; As[buf][lcol+1][lrow]=na0.y; As[buf][lcol+2][lrow]=na0.z; As[buf][lcol+3][lrow]=na0.w;
            As[buf][lcol+0][lrow+64]=na1.x; As[buf][lcol+1][lrow+64]=na1.y; As[buf][lcol+2][lrow+64]=na1.z; As[buf][lcol+3][lrow+64]=na1.w;
            Bs[buf][lcol+0][lrow]=nb0.x; Bs[buf][lcol+1][lrow]=nb0.y; Bs[buf][lcol+2][lrow]=nb0.z; Bs[buf][lcol+3][lrow]=nb0.w;
            Bs[buf][lcol+0][lrow+64]=nb1.x; Bs[buf][lcol+1][lrow+64]=nb1.y; Bs[buf][lcol+2][lrow+64]=nb1.z; Bs[buf][lcol+3][lrow+64]=nb1.w;
            __syncthreads();
        }
    }
#pragma unroll
    for (int i = 0; i < 8; i++) {
        const int row = blockIdx.y * 128 + ((i < 4) ? (ty * 4 + i) : (64 + ty * 4 + i - 4));
        const long long rbase = (long long)row * N;
#pragma unroll
        for (int p = 0; p < 4; p++) {
            const int col = blockIdx.x * 128 +
                            ((p < 2) ? (tx * 4 + p * 2) : (64 + tx * 4 + (p - 2) * 2));
            outp[rbase + col]     = __uint_as_float((unsigned)acc[i][p])         + bias[col];
            outp[rbase + col + 1] = __uint_as_float((unsigned)(acc[i][p] >> 32)) + bias[col + 1];
        }
    }
}

// ============================================================================
// Weight split: Whi/Wlo = bf16 hi/lo of block_W
// ============================================================================
__global__ void __launch_bounds__(256)
wsplit_kernel(const float* __restrict__ w)
{
    const long long e = ((long long)blockIdx.x * blockDim.x + threadIdx.x) << 2;
    const float4 v = *(const float4*)(w + e);
    __nv_bfloat16 h0 = __float2bfloat16(v.x), h1 = __float2bfloat16(v.y);
    __nv_bfloat16 h2 = __float2bfloat16(v.z), h3 = __float2bfloat16(v.w);
    __nv_bfloat16 l0 = __float2bfloat16(v.x - __bfloat162float(h0));
    __nv_bfloat16 l1 = __float2bfloat16(v.y - __bfloat162float(h1));
    __nv_bfloat16 l2 = __float2bfloat16(v.z - __bfloat162float(h2));
    __nv_bfloat16 l3 = __float2bfloat16(v.w - __bfloat162float(h3));
    ((__nv_bfloat162*)(g_Whi + e))[0] = __halves2bfloat162(h0, h1);
    ((__nv_bfloat162*)(g_Whi + e))[1] = __halves2bfloat162(h2, h3);
    ((__nv_bfloat162*)(g_Wlo + e))[0] = __halves2bfloat162(l0, l1);
    ((__nv_bfloat162*)(g_Wlo + e))[1] = __halves2bfloat162(l2, l3);
}

// ============================================================================
// Per-outer-step prep:
//   inp[n] = h[n] + (n==0 ? x_emb : h[n-1])   (h==0 on first step)
//   hi/loA = split( 0.5 * tanh(block_b[n] + inp[n]) )   (inner iter 1)
// ============================================================================
__global__ void __launch_bounds__(256)
prep_kernel(const float* __restrict__ blockb, int first)
{
    const long long e = ((long long)blockIdx.x * blockDim.x + threadIdx.x) << 2;
    const int n = (int)(e >> 20);
    const long long r = e & (BH - 1);
    const int d = (int)(e & (Hv - 1));

    float4 hv, bi;
    if (first) hv = make_float4(0.f, 0.f, 0.f, 0.f);
    else       hv = *(const float4*)&g_h[e];
    if (n == 0)      bi = *(const float4*)&g_xemb[r];
    else if (first)  bi = make_float4(0.f, 0.f, 0.f, 0.f);
    else             bi = *(const float4*)&g_h[e - BH];

    float4 v;
    v.x = hv.x + bi.x; v.y = hv.y + bi.y; v.z = hv.z + bi.z; v.w = hv.w + bi.w;
    *(float4*)&g_inp[e] = v;

    const float4 bb = *(const float4*)&blockb[n * Hv + d];
    const float t0 = 0.5f * tanhf(bb.x + v.x);
    const float t1 = 0.5f * tanhf(bb.y + v.y);
    const float t2 = 0.5f * tanhf(bb.z + v.z);
    const float t3 = 0.5f * tanhf(bb.w + v.w);
    __nv_bfloat16 h0 = __float2bfloat16(t0), h1 = __float2bfloat16(t1);
    __nv_bfloat16 h2 = __float2bfloat16(t2), h3 = __float2bfloat16(t3);
    __nv_bfloat16 l0 = __float2bfloat16(t0 - __bfloat162float(h0));
    __nv_bfloat16 l1 = __float2bfloat16(t1 - __bfloat162float(h1));
    __nv_bfloat16 l2 = __float2bfloat16(t2 - __bfloat162float(h2));
    __nv_bfloat16 l3 = __float2bfloat16(t3 - __bfloat162float(h3));
    ((__nv_bfloat162*)(g_hiA + e))[0] = __halves2bfloat162(h0, h1);
    ((__nv_bfloat162*)(g_hiA + e))[1] = __halves2bfloat162(h2, h3);
    ((__nv_bfloat162*)(g_loA + e))[0] = __halves2bfloat162(l0, l1);
    ((__nv_bfloat162*)(g_loA + e))[1] = __halves2bfloat162(l2, l3);
}

// ============================================================================
extern "C" void kernel_launch(void* const* d_in, const int* in_sizes, int n_in,
                              void* d_out, int out_size)
{
    const float* x     = (const float*)d_in[0];  // (B, DIN)
    const float* embW  = (const float*)d_in[1];  // (H, DIN)
    const float* embB  = (const float*)d_in[2];  // (H)
    const float* blkW  = (const float*)d_in[3];  // (NB, H, H)
    const float* blkB  = (const float*)d_in[4];  // (NB, H)
    const float* headW = (const float*)d_in[5];  // (DOUT, H)
    const float* headB = (const float*)d_in[6];  // (DOUT)
    float* out = (float*)d_out;                  // (B, DOUT)

    float *xemb, *h, *inp;
    __nv_bfloat16 *hiA, *loA, *hiB, *loB, *Whi, *Wlo;
    cudaGetSymbolAddress((void**)&xemb, g_xemb);
    cudaGetSymbolAddress((void**)&h,    g_h);
    cudaGetSymbolAddress((void**)&inp,  g_inp);
    cudaGetSymbolAddress((void**)&hiA,  g_hiA);
    cudaGetSymbolAddress((void**)&loA,  g_loA);
    cudaGetSymbolAddress((void**)&hiB,  g_hiB);
    cudaGetSymbolAddress((void**)&loB,  g_loB);
    cudaGetSymbolAddress((void**)&Whi,  g_Whi);
    cudaGetSymbolAddress((void**)&Wlo,  g_Wlo);

    cudaFuncSetAttribute(tgemm<1>, cudaFuncAttributeMaxDynamicSharedMemorySize, SMEM_DYN);
    cudaFuncSetAttribute(tgemm<2>, cudaFuncAttributeMaxDynamicSharedMemorySize, SMEM_DYN);

    const dim3 blk(256);

    // split weights into bf16 hi/lo (once per call)
    wsplit_kernel<<<(NBLK * HH / 4) / 256, blk>>>(blkW);

    // embed: x_emb = x @ embW^T + embB   (M=B, N=H, K=DIN)
    fgemm0<<<dim3(Hv / 128, Bv / 128, 1), blk>>>(x, embW, embB, xemb, Hv, DIN);

    const dim3 g(Hv / 128, (Bv + TMv - 1) / TMv, NBLK);   // (8, 11, 10) = 880 CTAs
    const int prep_blocks = (NBLK * BH / 4) / 256;

    for (int s = 0; s < STEPS; ++s) {
        const int first = (s == 0) ? 1 : 0;
        prep_kernel<<<prep_blocks, blk>>>(blkB, first);
        // inner iterations 2..4 (ping-pong hi/lo buffers)
        tgemm<1><<<g, blk, SMEM_DYN>>>(hiA, loA, Whi, Wlo, blkB, inp, hiB, loB, nullptr, 0);
        tgemm<1><<<g, blk, SMEM_DYN>>>(hiB, loB, Whi, Wlo, blkB, inp, hiA, loA, nullptr, 0);
        tgemm<1><<<g, blk, SMEM_DYN>>>(hiA, loA, Whi, Wlo, blkB, inp, hiB, loB, nullptr, 0);
        // inner iteration 5 fused with outer update
        tgemm<2><<<g, blk, SMEM_DYN>>>(hiB, loB, Whi, Wlo, blkB, inp, nullptr, nullptr, h, first);
    }

    // head: out = h[NB-1] @ headW^T + headB   (M=B, N=DOUT, K=H)
    fgemm0<<<dim3(DOUT / 128, Bv / 128, 1), blk>>>(
        h + (long long)(NBLK - 1) * BH, headW, headB, out, DOUT, Hv);
}